// round 1
// baseline (speedup 1.0000x reference)
#include <cuda_runtime.h>
#include <math.h>

#define LL 2048
#define BB 2
#define DD 256
#define PP 32
#define BL (BB*LL)

// ---------------- scratch (static device arrays; no allocations) ----------------
__device__ __align__(256) float g_content[BL*DD];
__device__ __align__(256) float g_values [BL*DD];
__device__ __align__(256) float g_ctx    [BL*DD];   // ctx, later reused as LN output
__device__ __align__(256) float g_sgh    [BL*128];
__device__ __align__(256) float g_gate   [BL];
__device__ __align__(256) float g_gcum   [BL];
__device__ __align__(256) float g_cpe    [BL*PP];
__device__ __align__(256) float g_offin  [BL*288];
__device__ __align__(256) float g_h1     [BL*512];
__device__ __align__(256) float g_Q1     [BL*64];
__device__ __align__(256) float g_K1     [LL*64];
__device__ __align__(256) float g_storage[BL*512];
__device__ __align__(256) float g_kvh    [BL*256];
__device__ __align__(256) float g_sp     [BL*PP];
__device__ __align__(256) float g_Q2     [BL*64];
__device__ __align__(256) float g_K2     [BL*64];
__device__ __align__(256) float g_Vk     [BL*DD];
__device__ __align__(256) float g_out1   [BL*DD];
__device__ __align__(256) float g_out2   [BL*DD];

__device__ __forceinline__ float gelu_f(float v){
    return 0.5f*v*(1.0f + erff(v*0.70710678118654752f));
}

// ---------------- generic tiled fp32 GEMM: C = act(A[M,K] @ W[N,K]^T + bias) (+addend) ----
template<int BN, int TN, int ACT, int ADD>
__global__ __launch_bounds__(128) void k_gemm(const float* __restrict__ A,
        const float* __restrict__ W, const float* __restrict__ bias,
        const float* __restrict__ addend, float* __restrict__ C, int K, int N){
    constexpr int BM = 64, BK = 16;
    __shared__ float As[BK][BM+4];
    __shared__ float Ws[BK][BN+4];
    int bm = blockIdx.x*BM, bn = blockIdx.y*BN;
    int t  = threadIdx.x;
    int tx = t & 7, ty = t >> 3;   // ty in [0,16)
    float acc[4][TN];
    #pragma unroll
    for (int i=0;i<4;i++)
        #pragma unroll
        for (int j=0;j<TN;j++) acc[i][j]=0.f;

    for (int k0=0; k0<K; k0+=BK){
        { // A tile 64x16
            int r = t>>1, kc = (t&1)*8;
            const float* ap = A + (size_t)(bm+r)*K + k0 + kc;
            float4 v0 = *(const float4*)ap;
            float4 v1 = *(const float4*)(ap+4);
            As[kc+0][r]=v0.x; As[kc+1][r]=v0.y; As[kc+2][r]=v0.z; As[kc+3][r]=v0.w;
            As[kc+4][r]=v1.x; As[kc+5][r]=v1.y; As[kc+6][r]=v1.z; As[kc+7][r]=v1.w;
        }
        if constexpr (BN==64){
            int r = t>>1, kc = (t&1)*8;
            const float* wp = W + (size_t)(bn+r)*K + k0 + kc;
            float4 v0 = *(const float4*)wp;
            float4 v1 = *(const float4*)(wp+4);
            Ws[kc+0][r]=v0.x; Ws[kc+1][r]=v0.y; Ws[kc+2][r]=v0.z; Ws[kc+3][r]=v0.w;
            Ws[kc+4][r]=v1.x; Ws[kc+5][r]=v1.y; Ws[kc+6][r]=v1.z; Ws[kc+7][r]=v1.w;
        } else {
            int r = t>>2, kc = (t&3)*4;
            float4 v0 = *(const float4*)(W + (size_t)(bn+r)*K + k0 + kc);
            Ws[kc+0][r]=v0.x; Ws[kc+1][r]=v0.y; Ws[kc+2][r]=v0.z; Ws[kc+3][r]=v0.w;
        }
        __syncthreads();
        #pragma unroll
        for (int kk=0; kk<BK; kk++){
            float4 a4 = *(const float4*)(&As[kk][ty*4]);
            float av[4] = {a4.x, a4.y, a4.z, a4.w};
            float wv[TN];
            if constexpr (TN==8){
                float4 w0 = *(const float4*)(&Ws[kk][tx*8]);
                float4 w1 = *(const float4*)(&Ws[kk][tx*8+4]);
                wv[0]=w0.x; wv[1]=w0.y; wv[2]=w0.z; wv[3]=w0.w;
                wv[4]=w1.x; wv[5]=w1.y; wv[6]=w1.z; wv[7]=w1.w;
            } else {
                float4 w0 = *(const float4*)(&Ws[kk][tx*4]);
                wv[0]=w0.x; wv[1]=w0.y; wv[2]=w0.z; wv[3]=w0.w;
            }
            #pragma unroll
            for (int i=0;i<4;i++)
                #pragma unroll
                for (int j=0;j<TN;j++) acc[i][j] += av[i]*wv[j];
        }
        __syncthreads();
    }
    #pragma unroll
    for (int i=0;i<4;i++){
        int row = bm + ty*4 + i;
        #pragma unroll
        for (int j=0;j<TN;j++){
            int col = bn + tx*TN + j;
            float v = acc[i][j] + bias[col];
            if constexpr (ACT==1) v = gelu_f(v);
            if constexpr (ADD)    v += addend[(size_t)row*N + col];
            C[(size_t)row*N + col] = v;
        }
    }
}

// ---------------- prep: offset_input, storage[:,0:256]=x, K1 pos trig ----------------
__global__ __launch_bounds__(256) void k_prep(const float* __restrict__ x,
                                              const float* __restrict__ pos){
    int row = blockIdx.x; int t = threadIdx.x;
    int b = row >> 11, l = row & 2047;
    float xv = x[(size_t)row*DD + t];
    g_offin[(size_t)row*288 + t]   = xv;
    g_storage[(size_t)row*512 + t] = xv;
    if (t < PP){
        float pp = pos[l*PP + t];
        g_offin[(size_t)row*288 + 256 + t] = pp;
        if (b == 0){
            float s, c; sincosf(pp, &s, &c);
            g_K1[l*64 + t] = c; g_K1[l*64 + 32 + t] = s;
        }
    }
}

// ---------------- hop head: off -> center/ww -> collapsed delta-sum -> Q1; gate; Vk ----
__global__ __launch_bounds__(256) void k_hop(const float* __restrict__ pos,
        const float* __restrict__ hop_w2, const float* __restrict__ hop_b2,
        const float* __restrict__ sg_w2,  const float* __restrict__ sg_b2){
    int row = blockIdx.x; int t = threadIdx.x;
    int l = row & 2047;
    __shared__ float h1s[512];
    __shared__ float sgs[128];
    __shared__ float offs[4][33];
    __shared__ float coefs[4];
    __shared__ float gateval;
    h1s[t]      = g_h1[(size_t)row*512 + t];
    h1s[t+256]  = g_h1[(size_t)row*512 + 256 + t];
    if (t < 128) sgs[t] = g_sgh[(size_t)row*128 + t];
    __syncthreads();
    if (t < 132){
        int h = t/33, p = t%33;
        const float* w2 = hop_w2 + (size_t)(h*33+p)*128;
        const float* hh = &h1s[h*128];
        float s = hop_b2[h*33+p];
        #pragma unroll 4
        for (int g=0; g<128; g++) s += hh[g]*w2[g];
        offs[h][p] = s;
    } else if (t >= 224){
        int lane = t - 224;
        float s = sgs[lane]*sg_w2[lane] + sgs[lane+32]*sg_w2[lane+32]
                + sgs[lane+64]*sg_w2[lane+64] + sgs[lane+96]*sg_w2[lane+96];
        #pragma unroll
        for (int o=16;o>0;o>>=1) s += __shfl_down_sync(0xffffffffu, s, o);
        if (lane==0){
            float gv = 1.0f/(1.0f+expf(-(s + sg_b2[0])));
            gateval = gv; g_gate[row] = gv;
        }
    }
    __syncthreads();
    if (t < 4){
        float ww  = 2.0f/(1.0f+expf(-offs[t][32])) + 0.1f;
        float w2v = ww*ww + 1e-6f;
        float e1 = expf(-0.5f/w2v);
        float e2 = expf(-2.0f/w2v);
        float totw = 1.0f + 2.0f*e1 + 2.0f*e2;
        coefs[t] = (1.0f + 2.0f*e1*0.9950041652780258f + 2.0f*e2*0.9800665778412416f)
                   / (totw + 1e-6f);
    }
    __syncthreads();
    if (t < PP){
        float pp = pos[l*PP + t];
        float ac=0.f, as=0.f;
        #pragma unroll
        for (int h=0; h<4; h++){
            float th = pp + tanhf(offs[h][t])*3.14159265358979323846f;
            float s, c; sincosf(th, &s, &c);
            ac += coefs[h]*c; as += coefs[h]*s;
        }
        const float s0 = 0.04419417382415922f; // 1/(4*sqrt(32))
        g_Q1[(size_t)row*64 + t]      = ac*s0;
        g_Q1[(size_t)row*64 + 32 + t] = as*s0;
    }
    float gv = gateval;
    g_Vk[(size_t)row*DD + t] = g_values[(size_t)row*DD + t]*gv;
}

// ---------------- serial scans: ctx_avg -> storage[:,256:512], gate_cum -> gcum --------
__global__ void k_scan(){
    int b = blockIdx.x, y = blockIdx.y, lane = threadIdx.x;
    if (y < 8){
        int c = y*32 + lane;
        float run = 0.f;
        const float* src = g_ctx + (size_t)b*LL*DD + c;
        float* dst = g_storage + (size_t)b*LL*512 + 256 + c;
        for (int l=0; l<LL; l++){
            run += src[(size_t)l*DD];
            dst[(size_t)l*512] = run * (1.0f/(float)(l+1));
        }
    } else {
        float carry = 0.f;
        for (int l0=0; l0<LL; l0+=32){
            float v = g_gate[b*LL + l0 + lane];
            #pragma unroll
            for (int o=1;o<32;o<<=1){
                float n = __shfl_up_sync(0xffffffffu, v, o);
                if (lane >= o) v += n;
            }
            float tot = __shfl_sync(0xffffffffu, v, 31);
            g_gcum[b*LL + l0 + lane] = fmaxf(v + carry, 1.0f);
            carry += tot;
        }
    }
}

// ---------------- Q2/K2 construction ----------------
__global__ void k_build2(){
    int row = blockIdx.x; int t = threadIdx.x; // 32 threads
    const float PIf = 3.14159265358979323846f;
    float spv = tanhf(g_sp[(size_t)row*PP + t])*PIf;
    float s, c; sincosf(spv, &s, &c);
    g_K2[(size_t)row*64 + t]      = c;
    g_K2[(size_t)row*64 + 32 + t] = s;
    float kp  = tanhf(g_cpe[(size_t)row*PP + t])*PIf;
    float inv = rsqrtf(g_gcum[row]) * 0.1767766952966369f; // 1/sqrt(32)
    sincosf(kp, &s, &c);
    g_Q2[(size_t)row*64 + t]      = c*inv;
    g_Q2[(size_t)row*64 + 32 + t] = s*inv;
}

// ---------------- fused causal attention (2 pseudo-heads), flash-style -----------------
__global__ __launch_bounds__(256) void k_attn(){
    int head = blockIdx.z, b = blockIdx.y;
    int qt = (gridDim.x - 1) - blockIdx.x;   // longest blocks first
    extern __shared__ float sm[];
    float* Qs = sm;                 // 32*65
    float* Ks = sm + 2080;          // 32*65
    float* Ss = sm + 4160;          // 32*33
    float* Vs = sm + 5216;          // 32*256
    const float* Q  = head ? g_Q2 + (size_t)b*LL*64 : g_Q1 + (size_t)b*LL*64;
    const float* Kp = head ? g_K2 + (size_t)b*LL*64 : g_K1;
    const float* V  = head ? g_Vk + (size_t)b*LL*DD : g_content + (size_t)b*LL*DD;
    float* O        = head ? g_out2 + (size_t)b*LL*DD : g_out1 + (size_t)b*LL*DD;
    int t = threadIdx.x;

    const float* Qt = Q + (size_t)qt*32*64;
    for (int idx=t; idx<2048; idx+=256) Qs[(idx>>6)*65 + (idx&63)] = Qt[idx];

    float acc[4][8];
    #pragma unroll
    for (int i=0;i<4;i++)
        #pragma unroll
        for (int j=0;j<8;j++) acc[i][j]=0.f;
    int rg = t>>5, cg = t&31;
    int r  = t>>3, kb = (t&7)*4;

    for (int kt=0; kt<=qt; kt++){
        __syncthreads();
        const float* Kt = Kp + (size_t)kt*32*64;
        for (int idx=t; idx<2048; idx+=256) Ks[(idx>>6)*65 + (idx&63)] = Kt[idx];
        const float* Vt = V + (size_t)kt*32*DD;
        for (int idx=t; idx<8192; idx+=256) Vs[idx] = Vt[idx];
        __syncthreads();
        // S tile: 32x32, K=64
        float sa[4] = {0.f,0.f,0.f,0.f};
        #pragma unroll 4
        for (int p=0;p<64;p++){
            float qv = Qs[r*65 + p];
            #pragma unroll
            for (int j=0;j<4;j++) sa[j] += qv*Ks[(kb+j)*65 + p];
        }
        if (kt == qt){
            #pragma unroll
            for (int j=0;j<4;j++) if (kb+j > r) sa[j] = 0.f;
        }
        #pragma unroll
        for (int j=0;j<4;j++) Ss[r*33 + kb + j] = sa[j];
        __syncthreads();
        // PV accumulate
        #pragma unroll 2
        for (int kk=0; kk<32; kk++){
            float s0v = Ss[(rg*4+0)*33+kk];
            float s1v = Ss[(rg*4+1)*33+kk];
            float s2v = Ss[(rg*4+2)*33+kk];
            float s3v = Ss[(rg*4+3)*33+kk];
            #pragma unroll
            for (int j=0;j<8;j++){
                float vv = Vs[kk*256 + cg + 32*j];
                acc[0][j] += s0v*vv; acc[1][j] += s1v*vv;
                acc[2][j] += s2v*vv; acc[3][j] += s3v*vv;
            }
        }
    }
    float* Ob = O + (size_t)qt*32*DD;
    #pragma unroll
    for (int i=0;i<4;i++)
        #pragma unroll
        for (int j=0;j<8;j++)
            Ob[(size_t)(rg*4+i)*256 + cg + 32*j] = acc[i][j];
}

// ---------------- layernorm ----------------
__global__ __launch_bounds__(256) void k_ln(const float* __restrict__ lng,
                                            const float* __restrict__ lnb){
    int row = blockIdx.x, t = threadIdx.x;
    float c = g_out1[(size_t)row*DD + t] + g_out2[(size_t)row*DD + t];
    float s = c, q = c*c;
    #pragma unroll
    for (int o=16;o>0;o>>=1){
        s += __shfl_down_sync(0xffffffffu, s, o);
        q += __shfl_down_sync(0xffffffffu, q, o);
    }
    __shared__ float ws[8], wq[8];
    __shared__ float mu_s, inv_s;
    if ((t&31)==0){ ws[t>>5]=s; wq[t>>5]=q; }
    __syncthreads();
    if (t==0){
        float S=0.f, Qq=0.f;
        #pragma unroll
        for (int i=0;i<8;i++){ S+=ws[i]; Qq+=wq[i]; }
        float mu = S*(1.0f/256.0f);
        float var = Qq*(1.0f/256.0f) - mu*mu;
        mu_s = mu; inv_s = rsqrtf(var + 1e-5f);
    }
    __syncthreads();
    float v = (c - mu_s)*inv_s*lng[t] + lnb[t];
    g_ctx[(size_t)row*DD + t] = v;   // reuse ctx buffer
}

// ---------------- launch ----------------
extern "C" void kernel_launch(void* const* d_in, const int* in_sizes, int n_in,
                              void* d_out, int out_size){
    const float* x         = (const float*)d_in[0];
    const float* pos       = (const float*)d_in[1];
    const float* w_content = (const float*)d_in[2];
    const float* b_content = (const float*)d_in[3];
    const float* hop_w1    = (const float*)d_in[4];
    const float* hop_b1    = (const float*)d_in[5];
    const float* hop_w2    = (const float*)d_in[6];
    const float* hop_b2    = (const float*)d_in[7];
    const float* w_cpe     = (const float*)d_in[8];
    const float* b_cpe     = (const float*)d_in[9];
    const float* w_val     = (const float*)d_in[10];
    const float* b_val     = (const float*)d_in[11];
    const float* w_ctx     = (const float*)d_in[12];
    const float* b_ctx     = (const float*)d_in[13];
    const float* kv_w1     = (const float*)d_in[14];
    const float* kv_b1     = (const float*)d_in[15];
    const float* kv_w2     = (const float*)d_in[16];
    const float* kv_b2     = (const float*)d_in[17];
    const float* sg_w1     = (const float*)d_in[18];
    const float* sg_b1     = (const float*)d_in[19];
    const float* sg_w2     = (const float*)d_in[20];
    const float* sg_b2     = (const float*)d_in[21];
    const float* ln_g      = (const float*)d_in[22];
    const float* ln_b      = (const float*)d_in[23];
    const float* w_out     = (const float*)d_in[24];
    const float* b_out     = (const float*)d_in[25];
    float* out = (float*)d_out;

    float *p_content, *p_values, *p_ctx, *p_sgh, *p_cpe, *p_offin, *p_h1,
          *p_storage, *p_kvh, *p_sp;
    cudaGetSymbolAddress((void**)&p_content, g_content);
    cudaGetSymbolAddress((void**)&p_values , g_values );
    cudaGetSymbolAddress((void**)&p_ctx    , g_ctx    );
    cudaGetSymbolAddress((void**)&p_sgh    , g_sgh    );
    cudaGetSymbolAddress((void**)&p_cpe    , g_cpe    );
    cudaGetSymbolAddress((void**)&p_offin  , g_offin  );
    cudaGetSymbolAddress((void**)&p_h1     , g_h1     );
    cudaGetSymbolAddress((void**)&p_storage, g_storage);
    cudaGetSymbolAddress((void**)&p_kvh    , g_kvh    );
    cudaGetSymbolAddress((void**)&p_sp     , g_sp     );

    cudaFuncSetAttribute(k_attn, cudaFuncAttributeMaxDynamicSharedMemorySize, 57344);

    k_prep<<<BL, 256>>>(x, pos);

    // projections of x
    k_gemm<64,8,0,0><<<dim3(64,4), 128>>>(x, w_content, b_content, nullptr, p_content, 256, 256);
    k_gemm<64,8,0,0><<<dim3(64,4), 128>>>(x, w_val,     b_val,     nullptr, p_values,  256, 256);
    k_gemm<64,8,0,0><<<dim3(64,4), 128>>>(x, w_ctx,     b_ctx,     nullptr, p_ctx,     256, 256);
    k_gemm<64,8,1,0><<<dim3(64,2), 128>>>(x, sg_w1,     sg_b1,     nullptr, p_sgh,     256, 128);
    k_gemm<32,4,0,0><<<dim3(64,1), 128>>>(x, w_cpe,     b_cpe,     nullptr, p_cpe,     256, 32);
    // hop MLP layer 1 (heads flattened: (4,128,288) -> (512,288))
    k_gemm<64,8,1,0><<<dim3(64,8), 128>>>(p_offin, hop_w1, hop_b1, nullptr, p_h1,      288, 512);

    k_hop<<<BL, 256>>>(pos, hop_w2, hop_b2, sg_w2, sg_b2);
    k_scan<<<dim3(BB,9), 32>>>();

    // kv MLP
    k_gemm<64,8,1,0><<<dim3(64,4), 128>>>(p_storage, kv_w1, kv_b1, nullptr, p_kvh, 512, 256);
    k_gemm<32,4,0,0><<<dim3(64,1), 128>>>(p_kvh,     kv_w2, kv_b2, nullptr, p_sp,  256, 32);

    k_build2<<<BL, 32>>>();

    k_attn<<<dim3(64, BB, 2), 256, 53632>>>();

    k_ln<<<BL, 256>>>(ln_g, ln_b);
    // out = x + ln @ w_out^T + b_out
    k_gemm<64,8,0,1><<<dim3(64,4), 128>>>(p_ctx, w_out, b_out, x, out, 256, 256);
}

// round 2
// speedup vs baseline: 2.8095x; 2.8095x over previous
#include <cuda_runtime.h>
#include <math.h>

#define LL 2048
#define BB 2
#define DD 256
#define PP 32
#define BL (BB*LL)

// ---------------- scratch ----------------
__device__ __align__(256) float g_content[BL*DD];
__device__ __align__(256) float g_values [BL*DD];
__device__ __align__(256) float g_ctx    [BL*DD];   // ctx, later reused as LN output
__device__ __align__(256) float g_sgh    [BL*128];
__device__ __align__(256) float g_gate   [BL];
__device__ __align__(256) float g_gcum   [BL];
__device__ __align__(256) float g_cpe    [BL*PP];
__device__ __align__(256) float g_offin  [BL*288];
__device__ __align__(256) float g_h1     [BL*512];
__device__ __align__(256) float g_Q1     [BL*64];
__device__ __align__(256) float g_K1     [LL*64];
__device__ __align__(256) float g_storage[BL*512];
__device__ __align__(256) float g_kvh    [BL*256];
__device__ __align__(256) float g_sp     [BL*PP];
__device__ __align__(256) float g_Q2     [BL*64];
__device__ __align__(256) float g_K2     [BL*64];
__device__ __align__(256) float g_Vk     [BL*DD];
__device__ __align__(256) float g_csum   [BB*16*256];
__device__ __align__(256) float g_part   [2u*8u*BL*DD];   // [head][kc][row][col]

__device__ __forceinline__ float gelu_f(float v){
    return 0.5f*v*(1.0f + erff(v*0.70710678118654752f));
}

// ---------------- generic tiled fp32 GEMM ----------------
template<int BN, int TN, int ACT, int ADD>
__global__ __launch_bounds__(128) void k_gemm(const float* __restrict__ A,
        const float* __restrict__ W, const float* __restrict__ bias,
        const float* __restrict__ addend, float* __restrict__ C, int K, int N){
    constexpr int BM = 64, BK = 16;
    __shared__ float As[BK][BM+4];
    __shared__ float Ws[BK][BN+4];
    int bm = blockIdx.x*BM, bn = blockIdx.y*BN;
    int t  = threadIdx.x;
    int tx = t & 7, ty = t >> 3;
    float acc[4][TN];
    #pragma unroll
    for (int i=0;i<4;i++)
        #pragma unroll
        for (int j=0;j<TN;j++) acc[i][j]=0.f;

    for (int k0=0; k0<K; k0+=BK){
        {
            int r = t>>1, kc = (t&1)*8;
            const float* ap = A + (size_t)(bm+r)*K + k0 + kc;
            float4 v0 = *(const float4*)ap;
            float4 v1 = *(const float4*)(ap+4);
            As[kc+0][r]=v0.x; As[kc+1][r]=v0.y; As[kc+2][r]=v0.z; As[kc+3][r]=v0.w;
            As[kc+4][r]=v1.x; As[kc+5][r]=v1.y; As[kc+6][r]=v1.z; As[kc+7][r]=v1.w;
        }
        if constexpr (BN==64){
            int r = t>>1, kc = (t&1)*8;
            const float* wp = W + (size_t)(bn+r)*K + k0 + kc;
            float4 v0 = *(const float4*)wp;
            float4 v1 = *(const float4*)(wp+4);
            Ws[kc+0][r]=v0.x; Ws[kc+1][r]=v0.y; Ws[kc+2][r]=v0.z; Ws[kc+3][r]=v0.w;
            Ws[kc+4][r]=v1.x; Ws[kc+5][r]=v1.y; Ws[kc+6][r]=v1.z; Ws[kc+7][r]=v1.w;
        } else {
            int r = t>>2, kc = (t&3)*4;
            float4 v0 = *(const float4*)(W + (size_t)(bn+r)*K + k0 + kc);
            Ws[kc+0][r]=v0.x; Ws[kc+1][r]=v0.y; Ws[kc+2][r]=v0.z; Ws[kc+3][r]=v0.w;
        }
        __syncthreads();
        #pragma unroll
        for (int kk=0; kk<BK; kk++){
            float4 a4 = *(const float4*)(&As[kk][ty*4]);
            float av[4] = {a4.x, a4.y, a4.z, a4.w};
            float wv[TN];
            if constexpr (TN==8){
                float4 w0 = *(const float4*)(&Ws[kk][tx*8]);
                float4 w1 = *(const float4*)(&Ws[kk][tx*8+4]);
                wv[0]=w0.x; wv[1]=w0.y; wv[2]=w0.z; wv[3]=w0.w;
                wv[4]=w1.x; wv[5]=w1.y; wv[6]=w1.z; wv[7]=w1.w;
            } else {
                float4 w0 = *(const float4*)(&Ws[kk][tx*4]);
                wv[0]=w0.x; wv[1]=w0.y; wv[2]=w0.z; wv[3]=w0.w;
            }
            #pragma unroll
            for (int i=0;i<4;i++)
                #pragma unroll
                for (int j=0;j<TN;j++) acc[i][j] += av[i]*wv[j];
        }
        __syncthreads();
    }
    #pragma unroll
    for (int i=0;i<4;i++){
        int row = bm + ty*4 + i;
        #pragma unroll
        for (int j=0;j<TN;j++){
            int col = bn + tx*TN + j;
            float v = acc[i][j] + bias[col];
            if constexpr (ACT==1) v = gelu_f(v);
            if constexpr (ADD)    v += addend[(size_t)row*N + col];
            C[(size_t)row*N + col] = v;
        }
    }
}

// ---------------- merged x-projection GEMM (5 segments, grid.y = 15) ----------------
__global__ __launch_bounds__(128) void k_gemm_multi(const float* __restrict__ A,
        const float* __restrict__ w_content, const float* __restrict__ b_content, float* __restrict__ p_content,
        const float* __restrict__ w_val,     const float* __restrict__ b_val,     float* __restrict__ p_values,
        const float* __restrict__ w_ctx,     const float* __restrict__ b_ctx,     float* __restrict__ p_ctx,
        const float* __restrict__ sg_w1,     const float* __restrict__ sg_b1,     float* __restrict__ p_sgh,
        const float* __restrict__ w_cpe,     const float* __restrict__ b_cpe,     float* __restrict__ p_cpe){
    constexpr int BM = 64, BK = 16, BN = 64;
    __shared__ float As[BK][BM+4];
    __shared__ float Ws[BK][BN+4];
    int y = blockIdx.y;
    int seg, bn, N; bool act=false, guard=false;
    if (y < 12){ seg = y>>2; bn = (y&3)*64; N = 256; }
    else if (y < 14){ seg = 3; bn = (y-12)*64; N = 128; act = true; }
    else { seg = 4; bn = 0; N = 32; guard = true; }
    const float* W; const float* Bv; float* C;
    if      (seg==0){ W=w_content; Bv=b_content; C=p_content; }
    else if (seg==1){ W=w_val;     Bv=b_val;     C=p_values;  }
    else if (seg==2){ W=w_ctx;     Bv=b_ctx;     C=p_ctx;     }
    else if (seg==3){ W=sg_w1;     Bv=sg_b1;     C=p_sgh;     }
    else            { W=w_cpe;     Bv=b_cpe;     C=p_cpe;     }

    int bm = blockIdx.x*BM;
    int t  = threadIdx.x;
    int tx = t & 7, ty = t >> 3;
    float acc[4][8];
    #pragma unroll
    for (int i=0;i<4;i++)
        #pragma unroll
        for (int j=0;j<8;j++) acc[i][j]=0.f;

    const int K = 256;
    for (int k0=0; k0<K; k0+=BK){
        {
            int r = t>>1, kc = (t&1)*8;
            const float* ap = A + (size_t)(bm+r)*K + k0 + kc;
            float4 v0 = *(const float4*)ap;
            float4 v1 = *(const float4*)(ap+4);
            As[kc+0][r]=v0.x; As[kc+1][r]=v0.y; As[kc+2][r]=v0.z; As[kc+3][r]=v0.w;
            As[kc+4][r]=v1.x; As[kc+5][r]=v1.y; As[kc+6][r]=v1.z; As[kc+7][r]=v1.w;
        }
        {
            int r = t>>1, kc = (t&1)*8;
            int wr = guard ? (r < 32 ? r : 31) : r;
            const float* wp = W + (size_t)(bn+wr)*K + k0 + kc;
            float4 v0 = *(const float4*)wp;
            float4 v1 = *(const float4*)(wp+4);
            Ws[kc+0][r]=v0.x; Ws[kc+1][r]=v0.y; Ws[kc+2][r]=v0.z; Ws[kc+3][r]=v0.w;
            Ws[kc+4][r]=v1.x; Ws[kc+5][r]=v1.y; Ws[kc+6][r]=v1.z; Ws[kc+7][r]=v1.w;
        }
        __syncthreads();
        #pragma unroll
        for (int kk=0; kk<BK; kk++){
            float4 a4 = *(const float4*)(&As[kk][ty*4]);
            float av[4] = {a4.x, a4.y, a4.z, a4.w};
            float4 w0 = *(const float4*)(&Ws[kk][tx*8]);
            float4 w1 = *(const float4*)(&Ws[kk][tx*8+4]);
            float wv[8] = {w0.x,w0.y,w0.z,w0.w,w1.x,w1.y,w1.z,w1.w};
            #pragma unroll
            for (int i=0;i<4;i++)
                #pragma unroll
                for (int j=0;j<8;j++) acc[i][j] += av[i]*wv[j];
        }
        __syncthreads();
    }
    #pragma unroll
    for (int i=0;i<4;i++){
        int row = bm + ty*4 + i;
        #pragma unroll
        for (int j=0;j<8;j++){
            int col = bn + tx*8 + j;
            if (guard && col >= 32) continue;
            float v = acc[i][j] + Bv[col];
            if (act) v = gelu_f(v);
            C[(size_t)row*N + col] = v;
        }
    }
}

// ---------------- prep ----------------
__global__ __launch_bounds__(256) void k_prep(const float* __restrict__ x,
                                              const float* __restrict__ pos){
    int row = blockIdx.x; int t = threadIdx.x;
    int b = row >> 11, l = row & 2047;
    float xv = x[(size_t)row*DD + t];
    g_offin[(size_t)row*288 + t]   = xv;
    g_storage[(size_t)row*512 + t] = xv;
    if (t < PP){
        float pp = pos[l*PP + t];
        g_offin[(size_t)row*288 + 256 + t] = pp;
        if (b == 0){
            float s, c; sincosf(pp, &s, &c);
            g_K1[l*64 + t] = c; g_K1[l*64 + 32 + t] = s;
        }
    }
}

// ---------------- hop head ----------------
__global__ __launch_bounds__(256) void k_hop(const float* __restrict__ pos,
        const float* __restrict__ hop_w2, const float* __restrict__ hop_b2,
        const float* __restrict__ sg_w2,  const float* __restrict__ sg_b2){
    int row = blockIdx.x; int t = threadIdx.x;
    int l = row & 2047;
    __shared__ float h1s[512];
    __shared__ float sgs[128];
    __shared__ float offs[132];
    __shared__ float coefs[4];
    __shared__ float gateval;
    h1s[t]      = g_h1[(size_t)row*512 + t];
    h1s[t+256]  = g_h1[(size_t)row*512 + 256 + t];
    if (t < 128) sgs[t] = g_sgh[(size_t)row*128 + t];
    __syncthreads();
    int w = t>>5, lane = t&31;
    // warp-cooperative dot products for 132 hop outputs
    for (int o = w; o < 132; o += 8){
        int h = o / 33;
        int p = o - h*33;
        const float4 hv = *(const float4*)(&h1s[h*128 + lane*4]);
        const float4 wv = *(const float4*)(hop_w2 + (size_t)(h*33+p)*128 + lane*4);
        float s = hv.x*wv.x + hv.y*wv.y + hv.z*wv.z + hv.w*wv.w;
        #pragma unroll
        for (int off=16; off>0; off>>=1) s += __shfl_down_sync(0xffffffffu, s, off);
        if (lane == 0) offs[o] = s + hop_b2[o];
    }
    if (w == 7){
        const float4 hv = *(const float4*)(&sgs[lane*4]);
        const float4 wv = *(const float4*)(sg_w2 + lane*4);
        float s = hv.x*wv.x + hv.y*wv.y + hv.z*wv.z + hv.w*wv.w;
        #pragma unroll
        for (int off=16; off>0; off>>=1) s += __shfl_down_sync(0xffffffffu, s, off);
        if (lane == 0){
            float gv = 1.0f/(1.0f+expf(-(s + sg_b2[0])));
            gateval = gv; g_gate[row] = gv;
        }
    }
    __syncthreads();
    if (t < 4){
        float ww  = 2.0f/(1.0f+expf(-offs[t*33+32])) + 0.1f;
        float w2v = ww*ww + 1e-6f;
        float e1 = expf(-0.5f/w2v);
        float e2 = expf(-2.0f/w2v);
        float totw = 1.0f + 2.0f*e1 + 2.0f*e2;
        coefs[t] = (1.0f + 2.0f*e1*0.9950041652780258f + 2.0f*e2*0.9800665778412416f)
                   / (totw + 1e-6f);
    }
    __syncthreads();
    if (t < PP){
        float pp = pos[l*PP + t];
        float ac=0.f, as=0.f;
        #pragma unroll
        for (int h=0; h<4; h++){
            float th = pp + tanhf(offs[h*33+t])*3.14159265358979323846f;
            float s, c; sincosf(th, &s, &c);
            ac += coefs[h]*c; as += coefs[h]*s;
        }
        const float s0 = 0.04419417382415922f; // 1/(4*sqrt(32))
        g_Q1[(size_t)row*64 + t]      = ac*s0;
        g_Q1[(size_t)row*64 + 32 + t] = as*s0;
    }
    float gv = gateval;
    g_Vk[(size_t)row*DD + t] = g_values[(size_t)row*DD + t]*gv;
}

// ---------------- chunked ctx_avg scan ----------------
__global__ __launch_bounds__(256) void k_scan1(){ // grid(BB,16)
    int b = blockIdx.x, ch = blockIdx.y, t = threadIdx.x;
    const float* src = g_ctx + ((size_t)(b*2048 + ch*128))*256 + t;
    float s = 0.f;
    #pragma unroll 4
    for (int l=0; l<128; l++) s += src[(size_t)l*256];
    g_csum[(b*16+ch)*256 + t] = s;
}

__global__ __launch_bounds__(256) void k_scan2(){ // grid(BB,16)
    int b = blockIdx.x, ch = blockIdx.y, t = threadIdx.x;
    float run = 0.f;
    for (int j=0; j<ch; j++) run += g_csum[(b*16+j)*256 + t];
    const float* src = g_ctx + ((size_t)(b*2048 + ch*128))*256 + t;
    float* dst = g_storage + ((size_t)(b*2048 + ch*128))*512 + 256 + t;
    int base = ch*128;
    #pragma unroll 4
    for (int l=0; l<128; l++){
        run += src[(size_t)l*256];
        dst[(size_t)l*512] = run / (float)(base + l + 1);
    }
}

__global__ void k_scang(){ // grid(BB), 32 thr: gate prefix
    int b = blockIdx.x, lane = threadIdx.x;
    float carry = 0.f;
    for (int l0=0; l0<LL; l0+=32){
        float v = g_gate[b*LL + l0 + lane];
        #pragma unroll
        for (int o=1;o<32;o<<=1){
            float n = __shfl_up_sync(0xffffffffu, v, o);
            if (lane >= o) v += n;
        }
        float tot = __shfl_sync(0xffffffffu, v, 31);
        g_gcum[b*LL + l0 + lane] = fmaxf(v + carry, 1.0f);
        carry += tot;
    }
}

// ---------------- Q2/K2 ----------------
__global__ void k_build2(){
    int row = blockIdx.x; int t = threadIdx.x; // 32 threads
    const float PIf = 3.14159265358979323846f;
    float spv = tanhf(g_sp[(size_t)row*PP + t])*PIf;
    float s, c; sincosf(spv, &s, &c);
    g_K2[(size_t)row*64 + t]      = c;
    g_K2[(size_t)row*64 + 32 + t] = s;
    float kp  = tanhf(g_cpe[(size_t)row*PP + t])*PIf;
    float inv = rsqrtf(g_gcum[row]) * 0.1767766952966369f; // 1/sqrt(32)
    sincosf(kp, &s, &c);
    g_Q2[(size_t)row*64 + t]      = c*inv;
    g_Q2[(size_t)row*64 + 32 + t] = s*inv;
}

// ---------------- split-KV causal attention ----------------
// TQ=64, TK=32, chunk = 8 KV tiles. grid (144, B, 2 heads), 256 threads.
// Writes deterministic partials into g_part[head][kc][row][col].
__global__ __launch_bounds__(256) void k_attn(){
    int head = blockIdx.z, b = blockIdx.y;
    int id = blockIdx.x;                    // 0..143
    int g = 0;
    while (id >= 2*(g+1)*(g+2)) g++;
    int e  = id - 2*g*(g+1);
    int qt = 4*g + e/(g+1);
    int kc = e - (e/(g+1))*(g+1);
    int kt0 = kc*8;
    int ktend = 2*qt + 2; if (ktend > kt0+8) ktend = kt0+8;

    extern __shared__ float sm[];
    float* Qs = sm;            // [64][65]
    float* Ks = sm + 4160;     // [32][65]
    float* Ss = sm + 6240;     // [32][72]  (Ss[kk][row])
    float* Vs = sm + 8544;     // [32][256]

    const float* Q  = head ? g_Q2 + (size_t)b*LL*64 : g_Q1 + (size_t)b*LL*64;
    const float* Kp = head ? g_K2 + (size_t)b*LL*64 : g_K1;
    const float* V  = head ? g_Vk + (size_t)b*LL*DD : g_content + (size_t)b*LL*DD;

    int t = threadIdx.x;
    // load Q tile 64x64
    const float* Qt = Q + (size_t)qt*64*64;
    for (int idx=t; idx<4096; idx+=256) Qs[(idx>>6)*65 + (idx&63)] = Qt[idx];

    float acc[8][8];
    #pragma unroll
    for (int i=0;i<8;i++)
        #pragma unroll
        for (int j=0;j<8;j++) acc[i][j]=0.f;

    int rS = t>>2, cgS = t&3;       // S phase: row 0..63, colgroup 0..3
    int rg = t>>5, lane = t&31;     // PV phase

    for (int kt=kt0; kt<ktend; kt++){
        __syncthreads();
        const float* Kt = Kp + (size_t)kt*32*64;
        for (int idx=t; idx<2048; idx+=256) Ks[(idx>>6)*65 + (idx&63)] = Kt[idx];
        const float* Vt = V + (size_t)kt*32*DD;
        const float4* Vt4 = (const float4*)Vt;
        float4* Vs4 = (float4*)Vs;
        for (int idx=t; idx<2048; idx+=256) Vs4[idx] = Vt4[idx];
        __syncthreads();
        // S tile: S[rS][cgS*8+j] = sum_p Q[rS][p] K[c][p]
        float sa[8] = {0.f,0.f,0.f,0.f,0.f,0.f,0.f,0.f};
        #pragma unroll 4
        for (int p=0; p<64; p++){
            float qv = Qs[rS*65 + p];
            #pragma unroll
            for (int j=0;j<8;j++) sa[j] += qv * Ks[(cgS*8+j)*65 + p];
        }
        if (kt >= 2*qt){   // diagonal tile: causal mask
            int rglob = qt*64 + rS;
            int cbase = kt*32 + cgS*8;
            #pragma unroll
            for (int j=0;j<8;j++) if (cbase+j > rglob) sa[j] = 0.f;
        }
        #pragma unroll
        for (int j=0;j<8;j++) Ss[(cgS*8+j)*72 + rS] = sa[j];
        __syncthreads();
        // PV: acc[i][j] += S[rg*8+i][kk] * V[kk][lane+32j]
        #pragma unroll 2
        for (int kk=0; kk<32; kk++){
            float4 sA = *(const float4*)(&Ss[kk*72 + rg*8]);
            float4 sB = *(const float4*)(&Ss[kk*72 + rg*8 + 4]);
            float sv[8] = {sA.x,sA.y,sA.z,sA.w,sB.x,sB.y,sB.z,sB.w};
            #pragma unroll
            for (int j=0;j<8;j++){
                float vv = Vs[kk*256 + lane + 32*j];
                #pragma unroll
                for (int i=0;i<8;i++) acc[i][j] += sv[i]*vv;
            }
        }
    }
    float* P = g_part + (((size_t)(head*8 + kc))*BL + (size_t)b*2048 + (size_t)qt*64 + rg*8)*256 + lane;
    #pragma unroll
    for (int i=0;i<8;i++)
        #pragma unroll
        for (int j=0;j<8;j++)
            P[(size_t)i*256 + 32*j] = acc[i][j];
}

// ---------------- layernorm (sums partials) ----------------
__global__ __launch_bounds__(256) void k_ln(const float* __restrict__ lng,
                                            const float* __restrict__ lnb){
    int row = blockIdx.x, t = threadIdx.x;
    int l = row & 2047;
    int nch = ((l >> 6) >> 2) + 1;   // chunks for this row's q-tile
    float c = 0.f;
    for (int kc=0; kc<nch; kc++){
        c += g_part[(((size_t)kc)*BL + row)*256 + t];
        c += g_part[(((size_t)(8+kc))*BL + row)*256 + t];
    }
    float s = c, q = c*c;
    #pragma unroll
    for (int o=16;o>0;o>>=1){
        s += __shfl_down_sync(0xffffffffu, s, o);
        q += __shfl_down_sync(0xffffffffu, q, o);
    }
    __shared__ float ws[8], wq[8];
    __shared__ float mu_s, inv_s;
    if ((t&31)==0){ ws[t>>5]=s; wq[t>>5]=q; }
    __syncthreads();
    if (t==0){
        float S=0.f, Qq=0.f;
        #pragma unroll
        for (int i=0;i<8;i++){ S+=ws[i]; Qq+=wq[i]; }
        float mu = S*(1.0f/256.0f);
        float var = Qq*(1.0f/256.0f) - mu*mu;
        mu_s = mu; inv_s = rsqrtf(var + 1e-5f);
    }
    __syncthreads();
    float v = (c - mu_s)*inv_s*lng[t] + lnb[t];
    g_ctx[(size_t)row*DD + t] = v;
}

// ---------------- launch ----------------
extern "C" void kernel_launch(void* const* d_in, const int* in_sizes, int n_in,
                              void* d_out, int out_size){
    const float* x         = (const float*)d_in[0];
    const float* pos       = (const float*)d_in[1];
    const float* w_content = (const float*)d_in[2];
    const float* b_content = (const float*)d_in[3];
    const float* hop_w1    = (const float*)d_in[4];
    const float* hop_b1    = (const float*)d_in[5];
    const float* hop_w2    = (const float*)d_in[6];
    const float* hop_b2    = (const float*)d_in[7];
    const float* w_cpe     = (const float*)d_in[8];
    const float* b_cpe     = (const float*)d_in[9];
    const float* w_val     = (const float*)d_in[10];
    const float* b_val     = (const float*)d_in[11];
    const float* w_ctx     = (const float*)d_in[12];
    const float* b_ctx     = (const float*)d_in[13];
    const float* kv_w1     = (const float*)d_in[14];
    const float* kv_b1     = (const float*)d_in[15];
    const float* kv_w2     = (const float*)d_in[16];
    const float* kv_b2     = (const float*)d_in[17];
    const float* sg_w1     = (const float*)d_in[18];
    const float* sg_b1     = (const float*)d_in[19];
    const float* sg_w2     = (const float*)d_in[20];
    const float* sg_b2     = (const float*)d_in[21];
    const float* ln_g      = (const float*)d_in[22];
    const float* ln_b      = (const float*)d_in[23];
    const float* w_out     = (const float*)d_in[24];
    const float* b_out     = (const float*)d_in[25];
    float* out = (float*)d_out;

    float *p_content, *p_values, *p_ctx, *p_sgh, *p_cpe, *p_offin, *p_h1,
          *p_storage, *p_kvh, *p_sp;
    cudaGetSymbolAddress((void**)&p_content, g_content);
    cudaGetSymbolAddress((void**)&p_values , g_values );
    cudaGetSymbolAddress((void**)&p_ctx    , g_ctx    );
    cudaGetSymbolAddress((void**)&p_sgh    , g_sgh    );
    cudaGetSymbolAddress((void**)&p_cpe    , g_cpe    );
    cudaGetSymbolAddress((void**)&p_offin  , g_offin  );
    cudaGetSymbolAddress((void**)&p_h1     , g_h1     );
    cudaGetSymbolAddress((void**)&p_storage, g_storage);
    cudaGetSymbolAddress((void**)&p_kvh    , g_kvh    );
    cudaGetSymbolAddress((void**)&p_sp     , g_sp     );

    cudaFuncSetAttribute(k_attn, cudaFuncAttributeMaxDynamicSharedMemorySize, 70000);

    k_prep<<<BL, 256>>>(x, pos);

    // all x-projections in one launch (960 blocks)
    k_gemm_multi<<<dim3(64,15), 128>>>(x,
        w_content, b_content, p_content,
        w_val,     b_val,     p_values,
        w_ctx,     b_ctx,     p_ctx,
        sg_w1,     sg_b1,     p_sgh,
        w_cpe,     b_cpe,     p_cpe);

    // hop MLP layer 1 (heads flattened (4,128,288) -> (512,288))
    k_gemm<64,8,1,0><<<dim3(64,8), 128>>>(p_offin, hop_w1, hop_b1, nullptr, p_h1, 288, 512);

    k_hop<<<BL, 256>>>(pos, hop_w2, hop_b2, sg_w2, sg_b2);

    k_scan1<<<dim3(BB,16), 256>>>();
    k_scang<<<BB, 32>>>();
    k_scan2<<<dim3(BB,16), 256>>>();

    // kv MLP
    k_gemm<64,8,1,0><<<dim3(64,4), 128>>>(p_storage, kv_w1, kv_b1, nullptr, p_kvh, 512, 256);
    k_gemm<32,4,0,0><<<dim3(64,1), 128>>>(p_kvh,     kv_w2, kv_b2, nullptr, p_sp,  256, 32);

    k_build2<<<BL, 32>>>();

    k_attn<<<dim3(144, BB, 2), 256, 66944>>>();

    k_ln<<<BL, 256>>>(ln_g, ln_b);
    k_gemm<64,8,0,1><<<dim3(64,4), 128>>>(p_ctx, w_out, b_out, x, out, 256, 256);
}

// round 3
// speedup vs baseline: 2.8950x; 1.0304x over previous
#include <cuda_runtime.h>
#include <math.h>

#define LL 2048
#define BB 2
#define DD 256
#define PP 32
#define BL (BB*LL)

// ---------------- scratch ----------------
__device__ __align__(256) float g_content[BL*DD];
__device__ __align__(256) float g_values [BL*DD];
__device__ __align__(256) float g_ctx    [BL*DD];   // ctx, later reused as LN output
__device__ __align__(256) float g_sgh    [BL*128];
__device__ __align__(256) float g_gate   [BL];
__device__ __align__(256) float g_gcum   [BL];
__device__ __align__(256) float g_cpe    [BL*PP];
__device__ __align__(256) float g_offin  [BL*288];
__device__ __align__(256) float g_h1     [BL*512];
__device__ __align__(256) float g_Q1     [BL*64];
__device__ __align__(256) float g_K1     [LL*64];
__device__ __align__(256) float g_storage[BL*512];
__device__ __align__(256) float g_kvh    [BL*256];
__device__ __align__(256) float g_sp     [BL*PP];
__device__ __align__(256) float g_Q2     [BL*64];
__device__ __align__(256) float g_K2     [BL*64];
__device__ __align__(256) float g_Vk     [BL*DD];
__device__ __align__(256) float g_csum   [BB*16*256];
__device__ __align__(256) float g_w2T    [128*132];
__device__ __align__(256) float g_part   [2u*8u*BL*DD];   // [head][kc][row][col]

__device__ __forceinline__ float gelu_f(float v){
    return 0.5f*v*(1.0f + erff(v*0.70710678118654752f));
}

// ---------------- hop_w2 transpose: [132][128] -> [128][132] ----------------
__global__ __launch_bounds__(256) void k_tw2(const float* __restrict__ hop_w2){
    int idx = blockIdx.x*256 + threadIdx.x;
    if (idx < 132*128){
        int o = idx >> 7, k = idx & 127;
        g_w2T[k*132 + o] = hop_w2[idx];
    }
}

// ---------------- generic tiled fp32 GEMM ----------------
template<int BM, int BN, int TN, int ACT, int ADD>
__global__ __launch_bounds__(128) void k_gemm(const float* __restrict__ A,
        const float* __restrict__ W, const float* __restrict__ bias,
        const float* __restrict__ addend, float* __restrict__ C, int K, int N){
    constexpr int BK = 16;
    constexpr int MR = BM/16;   // rows per thread
    __shared__ float As[BK][BM+4];
    __shared__ float Ws[BK][BN+4];
    int bm = blockIdx.x*BM, bn = blockIdx.y*BN;
    int t  = threadIdx.x;
    int tx = t & 7, ty = t >> 3;
    float acc[MR][TN];
    #pragma unroll
    for (int i=0;i<MR;i++)
        #pragma unroll
        for (int j=0;j<TN;j++) acc[i][j]=0.f;

    for (int k0=0; k0<K; k0+=BK){
        if constexpr (BM==64){
            int r = t>>1, kc = (t&1)*8;
            const float* ap = A + (size_t)(bm+r)*K + k0 + kc;
            float4 v0 = *(const float4*)ap;
            float4 v1 = *(const float4*)(ap+4);
            As[kc+0][r]=v0.x; As[kc+1][r]=v0.y; As[kc+2][r]=v0.z; As[kc+3][r]=v0.w;
            As[kc+4][r]=v1.x; As[kc+5][r]=v1.y; As[kc+6][r]=v1.z; As[kc+7][r]=v1.w;
        } else {
            int r = t>>2, kc = (t&3)*4;
            float4 v0 = *(const float4*)(A + (size_t)(bm+r)*K + k0 + kc);
            As[kc+0][r]=v0.x; As[kc+1][r]=v0.y; As[kc+2][r]=v0.z; As[kc+3][r]=v0.w;
        }
        if constexpr (BN==64){
            int r = t>>1, kc = (t&1)*8;
            const float* wp = W + (size_t)(bn+r)*K + k0 + kc;
            float4 v0 = *(const float4*)wp;
            float4 v1 = *(const float4*)(wp+4);
            Ws[kc+0][r]=v0.x; Ws[kc+1][r]=v0.y; Ws[kc+2][r]=v0.z; Ws[kc+3][r]=v0.w;
            Ws[kc+4][r]=v1.x; Ws[kc+5][r]=v1.y; Ws[kc+6][r]=v1.z; Ws[kc+7][r]=v1.w;
        } else {
            int r = t>>2, kc = (t&3)*4;
            float4 v0 = *(const float4*)(W + (size_t)(bn+r)*K + k0 + kc);
            Ws[kc+0][r]=v0.x; Ws[kc+1][r]=v0.y; Ws[kc+2][r]=v0.z; Ws[kc+3][r]=v0.w;
        }
        __syncthreads();
        #pragma unroll
        for (int kk=0; kk<BK; kk++){
            float av[MR];
            #pragma unroll
            for (int i=0;i<MR;i++) av[i] = As[kk][ty*MR+i];
            float wv[TN];
            if constexpr (TN==8){
                float4 w0 = *(const float4*)(&Ws[kk][tx*8]);
                float4 w1 = *(const float4*)(&Ws[kk][tx*8+4]);
                wv[0]=w0.x; wv[1]=w0.y; wv[2]=w0.z; wv[3]=w0.w;
                wv[4]=w1.x; wv[5]=w1.y; wv[6]=w1.z; wv[7]=w1.w;
            } else {
                float4 w0 = *(const float4*)(&Ws[kk][tx*4]);
                wv[0]=w0.x; wv[1]=w0.y; wv[2]=w0.z; wv[3]=w0.w;
            }
            #pragma unroll
            for (int i=0;i<MR;i++)
                #pragma unroll
                for (int j=0;j<TN;j++) acc[i][j] += av[i]*wv[j];
        }
        __syncthreads();
    }
    #pragma unroll
    for (int i=0;i<MR;i++){
        int row = bm + ty*MR + i;
        #pragma unroll
        for (int j=0;j<TN;j++){
            int col = bn + tx*TN + j;
            float v = acc[i][j] + bias[col];
            if constexpr (ACT==1) v = gelu_f(v);
            if constexpr (ADD)    v += addend[(size_t)row*N + col];
            C[(size_t)row*N + col] = v;
        }
    }
}

// ---------------- merged GEMM: 5 x-projections + hop layer1 (grid.y = 23) ----------------
__global__ __launch_bounds__(128) void k_gemm_multi(const float* __restrict__ x,
        const float* __restrict__ w_content, const float* __restrict__ b_content, float* __restrict__ p_content,
        const float* __restrict__ w_val,     const float* __restrict__ b_val,     float* __restrict__ p_values,
        const float* __restrict__ w_ctx,     const float* __restrict__ b_ctx,     float* __restrict__ p_ctx,
        const float* __restrict__ sg_w1,     const float* __restrict__ sg_b1,     float* __restrict__ p_sgh,
        const float* __restrict__ w_cpe,     const float* __restrict__ b_cpe,     float* __restrict__ p_cpe,
        const float* __restrict__ hop_w1,    const float* __restrict__ hop_b1,    float* __restrict__ p_h1,
        const float* __restrict__ p_offin){
    constexpr int BM = 64, BK = 16, BN = 64;
    __shared__ float As[BK][BM+4];
    __shared__ float Ws[BK][BN+4];
    int y = blockIdx.y;
    int seg, bn, N, K; bool act=false, guard=false;
    const float* A = x;
    if (y < 12){ seg = y>>2; bn = (y&3)*64; N = 256; K = 256; }
    else if (y < 14){ seg = 3; bn = (y-12)*64; N = 128; K = 256; act = true; }
    else if (y == 14){ seg = 4; bn = 0; N = 32; K = 256; guard = true; }
    else { seg = 5; bn = (y-15)*64; N = 512; K = 288; act = true; A = p_offin; }
    const float* W; const float* Bv; float* C;
    if      (seg==0){ W=w_content; Bv=b_content; C=p_content; }
    else if (seg==1){ W=w_val;     Bv=b_val;     C=p_values;  }
    else if (seg==2){ W=w_ctx;     Bv=b_ctx;     C=p_ctx;     }
    else if (seg==3){ W=sg_w1;     Bv=sg_b1;     C=p_sgh;     }
    else if (seg==4){ W=w_cpe;     Bv=b_cpe;     C=p_cpe;     }
    else            { W=hop_w1;    Bv=hop_b1;    C=p_h1;      }

    int bm = blockIdx.x*BM;
    int t  = threadIdx.x;
    int tx = t & 7, ty = t >> 3;
    float acc[4][8];
    #pragma unroll
    for (int i=0;i<4;i++)
        #pragma unroll
        for (int j=0;j<8;j++) acc[i][j]=0.f;

    for (int k0=0; k0<K; k0+=BK){
        {
            int r = t>>1, kc = (t&1)*8;
            const float* ap = A + (size_t)(bm+r)*K + k0 + kc;
            float4 v0 = *(const float4*)ap;
            float4 v1 = *(const float4*)(ap+4);
            As[kc+0][r]=v0.x; As[kc+1][r]=v0.y; As[kc+2][r]=v0.z; As[kc+3][r]=v0.w;
            As[kc+4][r]=v1.x; As[kc+5][r]=v1.y; As[kc+6][r]=v1.z; As[kc+7][r]=v1.w;
        }
        {
            int r = t>>1, kc = (t&1)*8;
            int wr = guard ? (r < 32 ? r : 31) : r;
            const float* wp = W + (size_t)(bn+wr)*K + k0 + kc;
            float4 v0 = *(const float4*)wp;
            float4 v1 = *(const float4*)(wp+4);
            Ws[kc+0][r]=v0.x; Ws[kc+1][r]=v0.y; Ws[kc+2][r]=v0.z; Ws[kc+3][r]=v0.w;
            Ws[kc+4][r]=v1.x; Ws[kc+5][r]=v1.y; Ws[kc+6][r]=v1.z; Ws[kc+7][r]=v1.w;
        }
        __syncthreads();
        #pragma unroll
        for (int kk=0; kk<BK; kk++){
            float4 a4 = *(const float4*)(&As[kk][ty*4]);
            float av[4] = {a4.x, a4.y, a4.z, a4.w};
            float4 w0 = *(const float4*)(&Ws[kk][tx*8]);
            float4 w1 = *(const float4*)(&Ws[kk][tx*8+4]);
            float wv[8] = {w0.x,w0.y,w0.z,w0.w,w1.x,w1.y,w1.z,w1.w};
            #pragma unroll
            for (int i=0;i<4;i++)
                #pragma unroll
                for (int j=0;j<8;j++) acc[i][j] += av[i]*wv[j];
        }
        __syncthreads();
    }
    #pragma unroll
    for (int i=0;i<4;i++){
        int row = bm + ty*4 + i;
        #pragma unroll
        for (int j=0;j<8;j++){
            int col = bn + tx*8 + j;
            if (guard && col >= 32) continue;
            float v = acc[i][j] + Bv[col];
            if (act) v = gelu_f(v);
            C[(size_t)row*N + col] = v;
        }
    }
}

// ---------------- prep ----------------
__global__ __launch_bounds__(256) void k_prep(const float* __restrict__ x,
                                              const float* __restrict__ pos){
    int row = blockIdx.x; int t = threadIdx.x;
    int b = row >> 11, l = row & 2047;
    float xv = x[(size_t)row*DD + t];
    g_offin[(size_t)row*288 + t]   = xv;
    g_storage[(size_t)row*512 + t] = xv;
    if (t < PP){
        float pp = pos[l*PP + t];
        g_offin[(size_t)row*288 + 256 + t] = pp;
        if (b == 0){
            float s, c; sincosf(pp, &s, &c);
            g_K1[l*64 + t] = c; g_K1[l*64 + 32 + t] = s;
        }
    }
}

// ---------------- hop head (no shuffles; transposed w2) ----------------
__global__ __launch_bounds__(256) void k_hop(const float* __restrict__ pos,
        const float* __restrict__ hop_b2,
        const float* __restrict__ sg_w2,  const float* __restrict__ sg_b2){
    int row = blockIdx.x; int t = threadIdx.x;
    int l = row & 2047;
    __shared__ float h1s[512];
    __shared__ float sgs[128];
    __shared__ float offs[132];
    __shared__ float coefs[4];
    __shared__ float gateval;
    if (t < 128) ((float4*)h1s)[t] = ((const float4*)(g_h1 + (size_t)row*512))[t];
    else if (t < 160) ((float4*)sgs)[t-128] = ((const float4*)(g_sgh + (size_t)row*128))[t-128];
    __syncthreads();
    int w = t>>5, lane = t&31;
    if (t < 132){
        int o = t;
        int h = o / 33;
        const float* hh = &h1s[h<<7];
        float s = 0.f;
        #pragma unroll 8
        for (int k=0;k<128;k++) s += hh[k]*g_w2T[k*132 + o];
        offs[o] = s + hop_b2[o];
    } else if (w == 7){
        const float4 hv = *(const float4*)(&sgs[lane*4]);
        const float4 wv = *(const float4*)(sg_w2 + lane*4);
        float s = hv.x*wv.x + hv.y*wv.y + hv.z*wv.z + hv.w*wv.w;
        #pragma unroll
        for (int off=16; off>0; off>>=1) s += __shfl_down_sync(0xffffffffu, s, off);
        if (lane == 0){
            float gv = 1.0f/(1.0f+expf(-(s + sg_b2[0])));
            gateval = gv; g_gate[row] = gv;
        }
    }
    __syncthreads();
    if (t < 4){
        float ww  = 2.0f/(1.0f+expf(-offs[t*33+32])) + 0.1f;
        float w2v = ww*ww + 1e-6f;
        float e1 = expf(-0.5f/w2v);
        float e2 = expf(-2.0f/w2v);
        float totw = 1.0f + 2.0f*e1 + 2.0f*e2;
        coefs[t] = (1.0f + 2.0f*e1*0.9950041652780258f + 2.0f*e2*0.9800665778412416f)
                   / (totw + 1e-6f);
    }
    __syncthreads();
    if (t < PP){
        float pp = pos[l*PP + t];
        float ac=0.f, as=0.f;
        #pragma unroll
        for (int h=0; h<4; h++){
            float th = pp + tanhf(offs[h*33+t])*3.14159265358979323846f;
            float s, c; sincosf(th, &s, &c);
            ac += coefs[h]*c; as += coefs[h]*s;
        }
        const float s0 = 0.04419417382415922f; // 1/(4*sqrt(32))
        g_Q1[(size_t)row*64 + t]      = ac*s0;
        g_Q1[(size_t)row*64 + 32 + t] = as*s0;
    }
    float gv = gateval;
    g_Vk[(size_t)row*DD + t] = g_values[(size_t)row*DD + t]*gv;
}

// ---------------- chunked ctx_avg scan ----------------
__global__ __launch_bounds__(256) void k_scan1(){ // grid(BB,16)
    int b = blockIdx.x, ch = blockIdx.y, t = threadIdx.x;
    const float* src = g_ctx + ((size_t)(b*2048 + ch*128))*256 + t;
    float s = 0.f;
    #pragma unroll 4
    for (int l=0; l<128; l++) s += src[(size_t)l*256];
    g_csum[(b*16+ch)*256 + t] = s;
}

__global__ __launch_bounds__(256) void k_scan2(){ // grid(BB,16)
    int b = blockIdx.x, ch = blockIdx.y, t = threadIdx.x;
    float run = 0.f;
    for (int j=0; j<ch; j++) run += g_csum[(b*16+j)*256 + t];
    const float* src = g_ctx + ((size_t)(b*2048 + ch*128))*256 + t;
    float* dst = g_storage + ((size_t)(b*2048 + ch*128))*512 + 256 + t;
    int base = ch*128;
    #pragma unroll 4
    for (int l=0; l<128; l++){
        run += src[(size_t)l*256];
        dst[(size_t)l*512] = run / (float)(base + l + 1);
    }
}

__global__ void k_scang(){ // grid(BB), 32 thr: gate prefix
    int b = blockIdx.x, lane = threadIdx.x;
    float carry = 0.f;
    for (int l0=0; l0<LL; l0+=32){
        float v = g_gate[b*LL + l0 + lane];
        #pragma unroll
        for (int o=1;o<32;o<<=1){
            float n = __shfl_up_sync(0xffffffffu, v, o);
            if (lane >= o) v += n;
        }
        float tot = __shfl_sync(0xffffffffu, v, 31);
        g_gcum[b*LL + l0 + lane] = fmaxf(v + carry, 1.0f);
        carry += tot;
    }
}

// ---------------- Q2/K2 ----------------
__global__ void k_build2(){
    int row = blockIdx.x; int t = threadIdx.x; // 32 threads
    const float PIf = 3.14159265358979323846f;
    float spv = tanhf(g_sp[(size_t)row*PP + t])*PIf;
    float s, c; sincosf(spv, &s, &c);
    g_K2[(size_t)row*64 + t]      = c;
    g_K2[(size_t)row*64 + 32 + t] = s;
    float kp  = tanhf(g_cpe[(size_t)row*PP + t])*PIf;
    float inv = rsqrtf(g_gcum[row]) * 0.1767766952966369f; // 1/sqrt(32)
    sincosf(kp, &s, &c);
    g_Q2[(size_t)row*64 + t]      = c*inv;
    g_Q2[(size_t)row*64 + 32 + t] = s*inv;
}

// ---------------- split-KV causal attention ----------------
__global__ __launch_bounds__(256) void k_attn(){
    int head = blockIdx.z, b = blockIdx.y;
    int id = blockIdx.x;                    // 0..143
    int g = 0;
    while (id >= 2*(g+1)*(g+2)) g++;
    int e  = id - 2*g*(g+1);
    int qt = 4*g + e/(g+1);
    int kc = e - (e/(g+1))*(g+1);
    int kt0 = kc*8;
    int ktend = 2*qt + 2; if (ktend > kt0+8) ktend = kt0+8;

    extern __shared__ float sm[];
    float* Qs = sm;            // [64][65]
    float* Ks = sm + 4160;     // [32][65]
    float* Ss = sm + 6240;     // [32][72]  (Ss[col][row])
    float* Vs = sm + 8544;     // [32][256]

    const float* Q  = head ? g_Q2 + (size_t)b*LL*64 : g_Q1 + (size_t)b*LL*64;
    const float* Kp = head ? g_K2 + (size_t)b*LL*64 : g_K1;
    const float* V  = head ? g_Vk + (size_t)b*LL*DD : g_content + (size_t)b*LL*DD;

    int t = threadIdx.x;
    const float* Qt = Q + (size_t)qt*64*64;
    for (int idx=t; idx<4096; idx+=256) Qs[(idx>>6)*65 + (idx&63)] = Qt[idx];

    float acc[8][8];
    #pragma unroll
    for (int i=0;i<8;i++)
        #pragma unroll
        for (int j=0;j<8;j++) acc[i][j]=0.f;

    int rg4 = t>>4, cg2 = t&15;     // S phase: 4 rows x 2 cols per thread
    int rg = t>>5, lane = t&31;     // PV phase: 8 rows x cols lane*8..+7

    for (int kt=kt0; kt<ktend; kt++){
        __syncthreads();
        const float* Kt = Kp + (size_t)kt*32*64;
        for (int idx=t; idx<2048; idx+=256) Ks[(idx>>6)*65 + (idx&63)] = Kt[idx];
        const float* Vt = V + (size_t)kt*32*DD;
        const float4* Vt4 = (const float4*)Vt;
        float4* Vs4 = (float4*)Vs;
        for (int idx=t; idx<2048; idx+=256) Vs4[idx] = Vt4[idx];
        __syncthreads();
        // S tile: sa[i][j] = sum_p Q[rg4*4+i][p] K[cg2*2+j][p]
        float sa[4][2];
        #pragma unroll
        for (int i=0;i<4;i++){ sa[i][0]=0.f; sa[i][1]=0.f; }
        #pragma unroll 4
        for (int p=0; p<64; p++){
            float kv0 = Ks[(cg2*2+0)*65 + p];
            float kv1 = Ks[(cg2*2+1)*65 + p];
            #pragma unroll
            for (int i=0;i<4;i++){
                float qv = Qs[(rg4*4+i)*65 + p];
                sa[i][0] += qv*kv0; sa[i][1] += qv*kv1;
            }
        }
        if (kt >= 2*qt){   // diagonal tile: causal mask
            #pragma unroll
            for (int i=0;i<4;i++){
                int rglob = qt*64 + rg4*4 + i;
                int cbase = kt*32 + cg2*2;
                if (cbase+0 > rglob) sa[i][0] = 0.f;
                if (cbase+1 > rglob) sa[i][1] = 0.f;
            }
        }
        #pragma unroll
        for (int i=0;i<4;i++){
            Ss[(cg2*2+0)*72 + rg4*4+i] = sa[i][0];
            Ss[(cg2*2+1)*72 + rg4*4+i] = sa[i][1];
        }
        __syncthreads();
        // PV: acc[i][j] += S[rg*8+i][kk] * V[kk][lane*8+j]
        #pragma unroll 2
        for (int kk=0; kk<32; kk++){
            float4 sA = *(const float4*)(&Ss[kk*72 + rg*8]);
            float4 sB = *(const float4*)(&Ss[kk*72 + rg*8 + 4]);
            float sv[8] = {sA.x,sA.y,sA.z,sA.w,sB.x,sB.y,sB.z,sB.w};
            float4 v0 = *(const float4*)(&Vs[kk*256 + lane*8]);
            float4 v1 = *(const float4*)(&Vs[kk*256 + lane*8 + 4]);
            float vv[8] = {v0.x,v0.y,v0.z,v0.w,v1.x,v1.y,v1.z,v1.w};
            #pragma unroll
            for (int i=0;i<8;i++)
                #pragma unroll
                for (int j=0;j<8;j++) acc[i][j] += sv[i]*vv[j];
        }
    }
    float* P = g_part + (((size_t)(head*8 + kc))*BL + (size_t)b*2048 + (size_t)qt*64 + rg*8)*256 + lane*8;
    #pragma unroll
    for (int i=0;i<8;i++){
        *(float4*)(&P[(size_t)i*256])     = make_float4(acc[i][0],acc[i][1],acc[i][2],acc[i][3]);
        *(float4*)(&P[(size_t)i*256 + 4]) = make_float4(acc[i][4],acc[i][5],acc[i][6],acc[i][7]);
    }
}

// ---------------- layernorm (sums partials) ----------------
__global__ __launch_bounds__(256) void k_ln(const float* __restrict__ lng,
                                            const float* __restrict__ lnb){
    int row = blockIdx.x, t = threadIdx.x;
    int l = row & 2047;
    int nch = ((l >> 6) >> 2) + 1;   // chunks for this row's q-tile
    float c = 0.f;
    for (int kc=0; kc<nch; kc++){
        c += g_part[(((size_t)kc)*BL + row)*256 + t];
        c += g_part[(((size_t)(8+kc))*BL + row)*256 + t];
    }
    float s = c, q = c*c;
    #pragma unroll
    for (int o=16;o>0;o>>=1){
        s += __shfl_down_sync(0xffffffffu, s, o);
        q += __shfl_down_sync(0xffffffffu, q, o);
    }
    __shared__ float ws[8], wq[8];
    __shared__ float mu_s, inv_s;
    if ((t&31)==0){ ws[t>>5]=s; wq[t>>5]=q; }
    __syncthreads();
    if (t==0){
        float S=0.f, Qq=0.f;
        #pragma unroll
        for (int i=0;i<8;i++){ S+=ws[i]; Qq+=wq[i]; }
        float mu = S*(1.0f/256.0f);
        float var = Qq*(1.0f/256.0f) - mu*mu;
        mu_s = mu; inv_s = rsqrtf(var + 1e-5f);
    }
    __syncthreads();
    float v = (c - mu_s)*inv_s*lng[t] + lnb[t];
    g_ctx[(size_t)row*DD + t] = v;
}

// ---------------- launch ----------------
extern "C" void kernel_launch(void* const* d_in, const int* in_sizes, int n_in,
                              void* d_out, int out_size){
    const float* x         = (const float*)d_in[0];
    const float* pos       = (const float*)d_in[1];
    const float* w_content = (const float*)d_in[2];
    const float* b_content = (const float*)d_in[3];
    const float* hop_w1    = (const float*)d_in[4];
    const float* hop_b1    = (const float*)d_in[5];
    const float* hop_w2    = (const float*)d_in[6];
    const float* hop_b2    = (const float*)d_in[7];
    const float* w_cpe     = (const float*)d_in[8];
    const float* b_cpe     = (const float*)d_in[9];
    const float* w_val     = (const float*)d_in[10];
    const float* b_val     = (const float*)d_in[11];
    const float* w_ctx     = (const float*)d_in[12];
    const float* b_ctx     = (const float*)d_in[13];
    const float* kv_w1     = (const float*)d_in[14];
    const float* kv_b1     = (const float*)d_in[15];
    const float* kv_w2     = (const float*)d_in[16];
    const float* kv_b2     = (const float*)d_in[17];
    const float* sg_w1     = (const float*)d_in[18];
    const float* sg_b1     = (const float*)d_in[19];
    const float* sg_w2     = (const float*)d_in[20];
    const float* sg_b2     = (const float*)d_in[21];
    const float* ln_g      = (const float*)d_in[22];
    const float* ln_b      = (const float*)d_in[23];
    const float* w_out     = (const float*)d_in[24];
    const float* b_out     = (const float*)d_in[25];
    float* out = (float*)d_out;

    float *p_content, *p_values, *p_ctx, *p_sgh, *p_cpe, *p_offin, *p_h1,
          *p_storage, *p_kvh, *p_sp;
    cudaGetSymbolAddress((void**)&p_content, g_content);
    cudaGetSymbolAddress((void**)&p_values , g_values );
    cudaGetSymbolAddress((void**)&p_ctx    , g_ctx    );
    cudaGetSymbolAddress((void**)&p_sgh    , g_sgh    );
    cudaGetSymbolAddress((void**)&p_cpe    , g_cpe    );
    cudaGetSymbolAddress((void**)&p_offin  , g_offin  );
    cudaGetSymbolAddress((void**)&p_h1     , g_h1     );
    cudaGetSymbolAddress((void**)&p_storage, g_storage);
    cudaGetSymbolAddress((void**)&p_kvh    , g_kvh    );
    cudaGetSymbolAddress((void**)&p_sp     , g_sp     );

    cudaFuncSetAttribute(k_attn, cudaFuncAttributeMaxDynamicSharedMemorySize, 70000);

    k_tw2<<<66, 256>>>(hop_w2);
    k_prep<<<BL, 256>>>(x, pos);

    // all x-projections + hop layer1 in one launch (1472 blocks)
    k_gemm_multi<<<dim3(64,23), 128>>>(x,
        w_content, b_content, p_content,
        w_val,     b_val,     p_values,
        w_ctx,     b_ctx,     p_ctx,
        sg_w1,     sg_b1,     p_sgh,
        w_cpe,     b_cpe,     p_cpe,
        hop_w1,    hop_b1,    p_h1,
        p_offin);

    k_hop<<<BL, 256>>>(pos, hop_b2, sg_w2, sg_b2);

    k_scan1<<<dim3(BB,16), 256>>>();
    k_scang<<<BB, 32>>>();
    k_scan2<<<dim3(BB,16), 256>>>();

    // kv MLP
    k_gemm<32,64,8,1,0><<<dim3(128,4), 128>>>(p_storage, kv_w1, kv_b1, nullptr, p_kvh, 512, 256);
    k_gemm<32,32,4,0,0><<<dim3(128,1), 128>>>(p_kvh,     kv_w2, kv_b2, nullptr, p_sp,  256, 32);

    k_build2<<<BL, 32>>>();

    k_attn<<<dim3(144, BB, 2), 256, 66944>>>();

    k_ln<<<BL, 256>>>(ln_g, ln_b);
    k_gemm<32,64,8,0,1><<<dim3(128,4), 128>>>(p_ctx, w_out, b_out, x, out, 256, 256);
}

// round 4
// speedup vs baseline: 4.9354x; 1.7048x over previous
#include <cuda_runtime.h>
#include <math.h>
#include <stdint.h>

#define LL 2048
#define BB 2
#define DD 256
#define PP 32
#define BL (BB*LL)

// ---------------- scratch ----------------
__device__ __align__(256) float g_content[BL*DD];
__device__ __align__(256) float g_values [BL*DD];
__device__ __align__(256) float g_ctx    [BL*DD];   // ctx, later reused as LN output
__device__ __align__(256) float g_sgh    [BL*128];
__device__ __align__(256) float g_gate   [BL];
__device__ __align__(256) float g_gcum   [BL];
__device__ __align__(256) float g_cpe    [BL*PP];
__device__ __align__(256) float g_offin  [BL*288];
__device__ __align__(256) float g_h1     [BL*512];
__device__ __align__(256) float g_Q1     [BL*64];
__device__ __align__(256) float g_K1     [LL*64];
__device__ __align__(256) float g_storage[BL*512];
__device__ __align__(256) float g_kvh    [BL*256];
__device__ __align__(256) float g_sp     [BL*PP];
__device__ __align__(256) float g_Q2     [BL*64];
__device__ __align__(256) float g_K2     [BL*64];
__device__ __align__(256) float g_Vk     [BL*DD];
__device__ __align__(256) float g_csum   [BB*16*256];
__device__ __align__(256) float g_w2T    [128*132];
__device__ __align__(256) float g_part   [2u*8u*BL*DD];   // [head][kc][row][col]

__device__ __forceinline__ float gelu_f(float v){
    return 0.5f*v*(1.0f + erff(v*0.70710678118654752f));
}

// ---------------- tf32 helpers ----------------
__device__ __forceinline__ uint32_t f2tf(float f){
    uint32_t u; asm("cvt.rna.tf32.f32 %0, %1;" : "=r"(u) : "f"(f)); return u;
}
__device__ __forceinline__ float f2tf_f(float f){ return __uint_as_float(f2tf(f)); }

__device__ __forceinline__ void mma8(float* c,
        uint32_t a0,uint32_t a1,uint32_t a2,uint32_t a3,
        uint32_t b0,uint32_t b1){
    asm volatile("mma.sync.aligned.m16n8k8.row.col.f32.tf32.tf32.f32 "
        "{%0,%1,%2,%3},{%4,%5,%6,%7},{%8,%9},{%0,%1,%2,%3};"
        : "+f"(c[0]),"+f"(c[1]),"+f"(c[2]),"+f"(c[3])
        : "r"(a0),"r"(a1),"r"(a2),"r"(a3),"r"(b0),"r"(b1));
}

// ---------------- hop_w2 transpose: [132][128] -> [128][132] ----------------
__global__ __launch_bounds__(256) void k_tw2(const float* __restrict__ hop_w2){
    int idx = blockIdx.x*256 + threadIdx.x;
    if (idx < 132*128){
        int o = idx >> 7, k = idx & 127;
        g_w2T[k*132 + o] = hop_w2[idx];
    }
}

// ---------------- tf32 GEMM core: C[M,N] = act(A @ W^T + bias) (+addend) ----------------
// block 128 thr, BM=64, BN=64, BK=16. guard => N==32 (single y tile).
__device__ __forceinline__ void gemm_core(const float* __restrict__ A,
        const float* __restrict__ W, const float* __restrict__ bias,
        const float* __restrict__ addend, float* __restrict__ C,
        int K, int N, int bm, int bn, bool act, bool guard, bool addres,
        float (*As)[20], float (*Ws)[20]){
    int t = threadIdx.x;
    int w = t>>5, lane = t&31, gr = lane>>2, ct = lane&3;
    int wm = (w&1)*32, wn = (w>>1)*32;
    float acc[2][4][4];
    #pragma unroll
    for (int mt=0;mt<2;mt++)
        #pragma unroll
        for (int nt=0;nt<4;nt++)
            #pragma unroll
            for (int i=0;i<4;i++) acc[mt][nt][i]=0.f;

    for (int k0=0; k0<K; k0+=16){
        #pragma unroll
        for (int i=0;i<2;i++){
            int idx = t + 128*i;
            int r = idx>>2, c4 = (idx&3)*4;
            float4 v = *(const float4*)(A + (size_t)(bm+r)*K + k0 + c4);
            As[r][c4+0]=f2tf_f(v.x); As[r][c4+1]=f2tf_f(v.y);
            As[r][c4+2]=f2tf_f(v.z); As[r][c4+3]=f2tf_f(v.w);
            int wr = guard ? (r<32?r:31) : r;
            float4 u = *(const float4*)(W + (size_t)(bn+wr)*K + k0 + c4);
            Ws[r][c4+0]=f2tf_f(u.x); Ws[r][c4+1]=f2tf_f(u.y);
            Ws[r][c4+2]=f2tf_f(u.z); Ws[r][c4+3]=f2tf_f(u.w);
        }
        __syncthreads();
        #pragma unroll
        for (int k8=0;k8<16;k8+=8){
            uint32_t a[2][4];
            #pragma unroll
            for (int mt=0;mt<2;mt++){
                a[mt][0]=__float_as_uint(As[wm+mt*16+gr  ][k8+ct  ]);
                a[mt][1]=__float_as_uint(As[wm+mt*16+gr+8][k8+ct  ]);
                a[mt][2]=__float_as_uint(As[wm+mt*16+gr  ][k8+ct+4]);
                a[mt][3]=__float_as_uint(As[wm+mt*16+gr+8][k8+ct+4]);
            }
            #pragma unroll
            for (int nt=0;nt<4;nt++){
                uint32_t b0=__float_as_uint(Ws[wn+nt*8+gr][k8+ct  ]);
                uint32_t b1=__float_as_uint(Ws[wn+nt*8+gr][k8+ct+4]);
                #pragma unroll
                for (int mt=0;mt<2;mt++)
                    mma8(acc[mt][nt], a[mt][0],a[mt][1],a[mt][2],a[mt][3], b0,b1);
            }
        }
        __syncthreads();
    }
    #pragma unroll
    for (int mt=0;mt<2;mt++){
        #pragma unroll
        for (int nt=0;nt<4;nt++){
            int lcol = wn + nt*8 + 2*ct;
            if (guard && lcol >= 32) continue;
            int col = bn + lcol;
            int r0 = bm + wm + mt*16 + gr;
            int r1 = r0 + 8;
            float b0v = bias[col], b1v = bias[col+1];
            float v00 = acc[mt][nt][0] + b0v;
            float v01 = acc[mt][nt][1] + b1v;
            float v10 = acc[mt][nt][2] + b0v;
            float v11 = acc[mt][nt][3] + b1v;
            if (act){ v00=gelu_f(v00); v01=gelu_f(v01); v10=gelu_f(v10); v11=gelu_f(v11); }
            if (addres){
                v00 += addend[(size_t)r0*N+col]; v01 += addend[(size_t)r0*N+col+1];
                v10 += addend[(size_t)r1*N+col]; v11 += addend[(size_t)r1*N+col+1];
            }
            C[(size_t)r0*N+col]   = v00;
            C[(size_t)r0*N+col+1] = v01;
            C[(size_t)r1*N+col]   = v10;
            C[(size_t)r1*N+col+1] = v11;
        }
    }
}

// ---------------- merged GEMM: 5 x-projections + hop layer1 (grid.y = 23) ----------------
__global__ __launch_bounds__(128) void k_gemm_multi_t(const float* __restrict__ x,
        const float* __restrict__ w_content, const float* __restrict__ b_content, float* __restrict__ p_content,
        const float* __restrict__ w_val,     const float* __restrict__ b_val,     float* __restrict__ p_values,
        const float* __restrict__ w_ctx,     const float* __restrict__ b_ctx,     float* __restrict__ p_ctx,
        const float* __restrict__ sg_w1,     const float* __restrict__ sg_b1,     float* __restrict__ p_sgh,
        const float* __restrict__ w_cpe,     const float* __restrict__ b_cpe,     float* __restrict__ p_cpe,
        const float* __restrict__ hop_w1,    const float* __restrict__ hop_b1,    float* __restrict__ p_h1,
        const float* __restrict__ p_offin){
    __shared__ float As[64][20];
    __shared__ float Ws[64][20];
    int y = blockIdx.y;
    int seg, bn, N, K; bool act=false, guard=false;
    const float* A = x;
    if (y < 12){ seg = y>>2; bn = (y&3)*64; N = 256; K = 256; }
    else if (y < 14){ seg = 3; bn = (y-12)*64; N = 128; K = 256; act = true; }
    else if (y == 14){ seg = 4; bn = 0; N = 32; K = 256; guard = true; }
    else { seg = 5; bn = (y-15)*64; N = 512; K = 288; act = true; A = p_offin; }
    const float* W; const float* Bv; float* C;
    if      (seg==0){ W=w_content; Bv=b_content; C=p_content; }
    else if (seg==1){ W=w_val;     Bv=b_val;     C=p_values;  }
    else if (seg==2){ W=w_ctx;     Bv=b_ctx;     C=p_ctx;     }
    else if (seg==3){ W=sg_w1;     Bv=sg_b1;     C=p_sgh;     }
    else if (seg==4){ W=w_cpe;     Bv=b_cpe;     C=p_cpe;     }
    else            { W=hop_w1;    Bv=hop_b1;    C=p_h1;      }
    gemm_core(A, W, Bv, nullptr, C, K, N, blockIdx.x*64, bn, act, guard, false, As, Ws);
}

// ---------------- generic single tf32 GEMM ----------------
__global__ __launch_bounds__(128) void k_gemm_t(const float* __restrict__ A,
        const float* __restrict__ W, const float* __restrict__ bias,
        const float* __restrict__ addend, float* __restrict__ C,
        int K, int N, int act, int guard, int addres){
    __shared__ float As[64][20];
    __shared__ float Ws[64][20];
    gemm_core(A, W, bias, addend, C, K, N, blockIdx.x*64, blockIdx.y*64,
              act!=0, guard!=0, addres!=0, As, Ws);
}

// ---------------- prep ----------------
__global__ __launch_bounds__(256) void k_prep(const float* __restrict__ x,
                                              const float* __restrict__ pos){
    int row = blockIdx.x; int t = threadIdx.x;
    int b = row >> 11, l = row & 2047;
    float xv = x[(size_t)row*DD + t];
    g_offin[(size_t)row*288 + t]   = xv;
    g_storage[(size_t)row*512 + t] = xv;
    if (t < PP){
        float pp = pos[l*PP + t];
        g_offin[(size_t)row*288 + 256 + t] = pp;
        if (b == 0){
            float s, c; sincosf(pp, &s, &c);
            g_K1[l*64 + t] = c; g_K1[l*64 + 32 + t] = s;
        }
    }
}

// ---------------- hop head ----------------
__global__ __launch_bounds__(256) void k_hop(const float* __restrict__ pos,
        const float* __restrict__ hop_b2,
        const float* __restrict__ sg_w2,  const float* __restrict__ sg_b2){
    int row = blockIdx.x; int t = threadIdx.x;
    int l = row & 2047;
    __shared__ float h1s[512];
    __shared__ float sgs[128];
    __shared__ float offs[132];
    __shared__ float coefs[4];
    __shared__ float gateval;
    if (t < 128) ((float4*)h1s)[t] = ((const float4*)(g_h1 + (size_t)row*512))[t];
    else if (t < 160) ((float4*)sgs)[t-128] = ((const float4*)(g_sgh + (size_t)row*128))[t-128];
    __syncthreads();
    int w = t>>5, lane = t&31;
    if (t < 132){
        int o = t;
        int h = o / 33;
        const float* hh = &h1s[h<<7];
        float s = 0.f;
        #pragma unroll 8
        for (int k=0;k<128;k++) s += hh[k]*g_w2T[k*132 + o];
        offs[o] = s + hop_b2[o];
    } else if (w == 7){
        const float4 hv = *(const float4*)(&sgs[lane*4]);
        const float4 wv = *(const float4*)(sg_w2 + lane*4);
        float s = hv.x*wv.x + hv.y*wv.y + hv.z*wv.z + hv.w*wv.w;
        #pragma unroll
        for (int off=16; off>0; off>>=1) s += __shfl_down_sync(0xffffffffu, s, off);
        if (lane == 0){
            float gv = 1.0f/(1.0f+expf(-(s + sg_b2[0])));
            gateval = gv; g_gate[row] = gv;
        }
    }
    __syncthreads();
    if (t < 4){
        float ww  = 2.0f/(1.0f+expf(-offs[t*33+32])) + 0.1f;
        float w2v = ww*ww + 1e-6f;
        float e1 = expf(-0.5f/w2v);
        float e2 = expf(-2.0f/w2v);
        float totw = 1.0f + 2.0f*e1 + 2.0f*e2;
        coefs[t] = (1.0f + 2.0f*e1*0.9950041652780258f + 2.0f*e2*0.9800665778412416f)
                   / (totw + 1e-6f);
    }
    __syncthreads();
    if (t < PP){
        float pp = pos[l*PP + t];
        float ac=0.f, as=0.f;
        #pragma unroll
        for (int h=0; h<4; h++){
            float th = pp + tanhf(offs[h*33+t])*3.14159265358979323846f;
            float s, c; sincosf(th, &s, &c);
            ac += coefs[h]*c; as += coefs[h]*s;
        }
        const float s0 = 0.04419417382415922f; // 1/(4*sqrt(32))
        g_Q1[(size_t)row*64 + t]      = ac*s0;
        g_Q1[(size_t)row*64 + 32 + t] = as*s0;
    }
    float gv = gateval;
    g_Vk[(size_t)row*DD + t] = g_values[(size_t)row*DD + t]*gv;
}

// ---------------- chunked ctx_avg scan ----------------
__global__ __launch_bounds__(256) void k_scan1(){ // grid(BB,16)
    int b = blockIdx.x, ch = blockIdx.y, t = threadIdx.x;
    const float* src = g_ctx + ((size_t)(b*2048 + ch*128))*256 + t;
    float s = 0.f;
    #pragma unroll 4
    for (int l=0; l<128; l++) s += src[(size_t)l*256];
    g_csum[(b*16+ch)*256 + t] = s;
}

__global__ __launch_bounds__(256) void k_scan2(){ // grid(BB,16)
    int b = blockIdx.x, ch = blockIdx.y, t = threadIdx.x;
    float run = 0.f;
    for (int j=0; j<ch; j++) run += g_csum[(b*16+j)*256 + t];
    const float* src = g_ctx + ((size_t)(b*2048 + ch*128))*256 + t;
    float* dst = g_storage + ((size_t)(b*2048 + ch*128))*512 + 256 + t;
    int base = ch*128;
    #pragma unroll 4
    for (int l=0; l<128; l++){
        run += src[(size_t)l*256];
        dst[(size_t)l*512] = run / (float)(base + l + 1);
    }
}

__global__ void k_scang(){ // grid(BB), 32 thr
    int b = blockIdx.x, lane = threadIdx.x;
    float carry = 0.f;
    for (int l0=0; l0<LL; l0+=32){
        float v = g_gate[b*LL + l0 + lane];
        #pragma unroll
        for (int o=1;o<32;o<<=1){
            float n = __shfl_up_sync(0xffffffffu, v, o);
            if (lane >= o) v += n;
        }
        float tot = __shfl_sync(0xffffffffu, v, 31);
        g_gcum[b*LL + l0 + lane] = fmaxf(v + carry, 1.0f);
        carry += tot;
    }
}

// ---------------- Q2/K2 ----------------
__global__ void k_build2(){
    int row = blockIdx.x; int t = threadIdx.x; // 32 threads
    const float PIf = 3.14159265358979323846f;
    float spv = tanhf(g_sp[(size_t)row*PP + t])*PIf;
    float s, c; sincosf(spv, &s, &c);
    g_K2[(size_t)row*64 + t]      = c;
    g_K2[(size_t)row*64 + 32 + t] = s;
    float kp  = tanhf(g_cpe[(size_t)row*PP + t])*PIf;
    float inv = rsqrtf(g_gcum[row]) * 0.1767766952966369f; // 1/sqrt(32)
    sincosf(kp, &s, &c);
    g_Q2[(size_t)row*64 + t]      = c*inv;
    g_Q2[(size_t)row*64 + 32 + t] = s*inv;
}

// ---------------- split-KV causal attention (tf32 mma) ----------------
// TQ=64, TK=32, chunk=8 KV tiles. grid (144, B, 2 heads), 256 threads (8 warps).
__global__ __launch_bounds__(256) void k_attn(){
    int head = blockIdx.z, b = blockIdx.y;
    int id = blockIdx.x;                    // 0..143
    int g = 0;
    while (id >= 2*(g+1)*(g+2)) g++;
    int e  = id - 2*g*(g+1);
    int qt = 4*g + e/(g+1);
    int kc = e - (e/(g+1))*(g+1);
    int kt0 = kc*8;
    int ktend = 2*qt + 2; if (ktend > kt0+8) ktend = kt0+8;

    extern __shared__ float sm[];
    float* Qs = sm;              // [64][65]
    float* Ks = sm + 4160;       // [32][65]
    float* Ss = sm + 6240;       // [64][33]
    float* Vs = sm + 8352;       // [32][264]

    const float* Q  = head ? g_Q2 + (size_t)b*LL*64 : g_Q1 + (size_t)b*LL*64;
    const float* Kp = head ? g_K2 + (size_t)b*LL*64 : g_K1;
    const float* V  = head ? g_Vk + (size_t)b*LL*DD : g_content + (size_t)b*LL*DD;

    int t = threadIdx.x;
    int w = t>>5, lane = t&31, gr = lane>>2, ct = lane&3;

    const float* Qt = Q + (size_t)qt*64*64;
    for (int idx=t; idx<4096; idx+=256)
        Qs[(idx>>6)*65 + (idx&63)] = f2tf_f(Qt[idx]);

    float acc[16][4];
    #pragma unroll
    for (int i=0;i<16;i++){ acc[i][0]=0.f; acc[i][1]=0.f; acc[i][2]=0.f; acc[i][3]=0.f; }

    int wmS = (w&3)*16, wnS = (w>>2)*16;
    int wmP = (w&3)*16, wnP = (w>>2)*128;

    for (int kt=kt0; kt<ktend; kt++){
        __syncthreads();
        const float* Kt = Kp + (size_t)kt*32*64;
        for (int idx=t; idx<2048; idx+=256)
            Ks[(idx>>6)*65 + (idx&63)] = f2tf_f(Kt[idx]);
        const float4* Vt4 = (const float4*)(V + (size_t)kt*32*DD);
        for (int idx=t; idx<2048; idx+=256){
            int r = idx>>6, c4 = idx&63;
            float4 v = Vt4[idx];
            float* d = Vs + r*264 + c4*4;
            d[0]=f2tf_f(v.x); d[1]=f2tf_f(v.y); d[2]=f2tf_f(v.z); d[3]=f2tf_f(v.w);
        }
        __syncthreads();
        // ---- S = Q @ K^T (64x32, K=64) ----
        float cS[2][4];
        #pragma unroll
        for (int nt=0;nt<2;nt++){ cS[nt][0]=0.f; cS[nt][1]=0.f; cS[nt][2]=0.f; cS[nt][3]=0.f; }
        #pragma unroll
        for (int k8=0;k8<64;k8+=8){
            uint32_t a0=__float_as_uint(Qs[(wmS+gr  )*65 + k8+ct  ]);
            uint32_t a1=__float_as_uint(Qs[(wmS+gr+8)*65 + k8+ct  ]);
            uint32_t a2=__float_as_uint(Qs[(wmS+gr  )*65 + k8+ct+4]);
            uint32_t a3=__float_as_uint(Qs[(wmS+gr+8)*65 + k8+ct+4]);
            #pragma unroll
            for (int nt=0;nt<2;nt++){
                uint32_t b0=__float_as_uint(Ks[(wnS+nt*8+gr)*65 + k8+ct  ]);
                uint32_t b1=__float_as_uint(Ks[(wnS+nt*8+gr)*65 + k8+ct+4]);
                mma8(cS[nt], a0,a1,a2,a3, b0,b1);
            }
        }
        bool diag = (kt >= 2*qt);
        #pragma unroll
        for (int nt=0;nt<2;nt++){
            int col0 = wnS + nt*8 + 2*ct;
            int r0 = wmS + gr, r1 = r0 + 8;
            float v00=cS[nt][0], v01=cS[nt][1], v10=cS[nt][2], v11=cS[nt][3];
            if (diag){
                int gcol = kt*32 + col0;
                int grow0 = qt*64 + r0, grow1 = qt*64 + r1;
                if (gcol   > grow0) v00 = 0.f;
                if (gcol+1 > grow0) v01 = 0.f;
                if (gcol   > grow1) v10 = 0.f;
                if (gcol+1 > grow1) v11 = 0.f;
            }
            Ss[r0*33+col0]   = f2tf_f(v00);
            Ss[r0*33+col0+1] = f2tf_f(v01);
            Ss[r1*33+col0]   = f2tf_f(v10);
            Ss[r1*33+col0+1] = f2tf_f(v11);
        }
        __syncthreads();
        // ---- acc += S @ V (64x256, K=32) ----
        #pragma unroll
        for (int k8=0;k8<32;k8+=8){
            uint32_t a0=__float_as_uint(Ss[(wmP+gr  )*33 + k8+ct  ]);
            uint32_t a1=__float_as_uint(Ss[(wmP+gr+8)*33 + k8+ct  ]);
            uint32_t a2=__float_as_uint(Ss[(wmP+gr  )*33 + k8+ct+4]);
            uint32_t a3=__float_as_uint(Ss[(wmP+gr+8)*33 + k8+ct+4]);
            #pragma unroll
            for (int nt=0;nt<16;nt++){
                uint32_t b0=__float_as_uint(Vs[(k8+ct  )*264 + wnP + nt*8 + gr]);
                uint32_t b1=__float_as_uint(Vs[(k8+ct+4)*264 + wnP + nt*8 + gr]);
                mma8(acc[nt], a0,a1,a2,a3, b0,b1);
            }
        }
    }
    float* P = g_part + (((size_t)(head*8 + kc))*BL + (size_t)b*2048 + (size_t)qt*64)*256;
    #pragma unroll
    for (int nt=0;nt<16;nt++){
        int col = wnP + nt*8 + 2*ct;
        int r0 = wmP + gr, r1 = r0 + 8;
        *(float2*)(P + (size_t)r0*256 + col) = make_float2(acc[nt][0], acc[nt][1]);
        *(float2*)(P + (size_t)r1*256 + col) = make_float2(acc[nt][2], acc[nt][3]);
    }
}

// ---------------- layernorm (sums partials) ----------------
__global__ __launch_bounds__(256) void k_ln(const float* __restrict__ lng,
                                            const float* __restrict__ lnb){
    int row = blockIdx.x, t = threadIdx.x;
    int l = row & 2047;
    int nch = ((l >> 6) >> 2) + 1;
    float c = 0.f;
    for (int kc=0; kc<nch; kc++){
        c += g_part[(((size_t)kc)*BL + row)*256 + t];
        c += g_part[(((size_t)(8+kc))*BL + row)*256 + t];
    }
    float s = c, q = c*c;
    #pragma unroll
    for (int o=16;o>0;o>>=1){
        s += __shfl_down_sync(0xffffffffu, s, o);
        q += __shfl_down_sync(0xffffffffu, q, o);
    }
    __shared__ float ws[8], wq[8];
    __shared__ float mu_s, inv_s;
    if ((t&31)==0){ ws[t>>5]=s; wq[t>>5]=q; }
    __syncthreads();
    if (t==0){
        float S=0.f, Qq=0.f;
        #pragma unroll
        for (int i=0;i<8;i++){ S+=ws[i]; Qq+=wq[i]; }
        float mu = S*(1.0f/256.0f);
        float var = Qq*(1.0f/256.0f) - mu*mu;
        mu_s = mu; inv_s = rsqrtf(var + 1e-5f);
    }
    __syncthreads();
    float v = (c - mu_s)*inv_s*lng[t] + lnb[t];
    g_ctx[(size_t)row*DD + t] = v;
}

// ---------------- launch ----------------
extern "C" void kernel_launch(void* const* d_in, const int* in_sizes, int n_in,
                              void* d_out, int out_size){
    const float* x         = (const float*)d_in[0];
    const float* pos       = (const float*)d_in[1];
    const float* w_content = (const float*)d_in[2];
    const float* b_content = (const float*)d_in[3];
    const float* hop_w1    = (const float*)d_in[4];
    const float* hop_b1    = (const float*)d_in[5];
    const float* hop_w2    = (const float*)d_in[6];
    const float* hop_b2    = (const float*)d_in[7];
    const float* w_cpe     = (const float*)d_in[8];
    const float* b_cpe     = (const float*)d_in[9];
    const float* w_val     = (const float*)d_in[10];
    const float* b_val     = (const float*)d_in[11];
    const float* w_ctx     = (const float*)d_in[12];
    const float* b_ctx     = (const float*)d_in[13];
    const float* kv_w1     = (const float*)d_in[14];
    const float* kv_b1     = (const float*)d_in[15];
    const float* kv_w2     = (const float*)d_in[16];
    const float* kv_b2     = (const float*)d_in[17];
    const float* sg_w1     = (const float*)d_in[18];
    const float* sg_b1     = (const float*)d_in[19];
    const float* sg_w2     = (const float*)d_in[20];
    const float* sg_b2     = (const float*)d_in[21];
    const float* ln_g      = (const float*)d_in[22];
    const float* ln_b      = (const float*)d_in[23];
    const float* w_out     = (const float*)d_in[24];
    const float* b_out     = (const float*)d_in[25];
    float* out = (float*)d_out;

    float *p_content, *p_values, *p_ctx, *p_sgh, *p_cpe, *p_offin, *p_h1,
          *p_storage, *p_kvh, *p_sp;
    cudaGetSymbolAddress((void**)&p_content, g_content);
    cudaGetSymbolAddress((void**)&p_values , g_values );
    cudaGetSymbolAddress((void**)&p_ctx    , g_ctx    );
    cudaGetSymbolAddress((void**)&p_sgh    , g_sgh    );
    cudaGetSymbolAddress((void**)&p_cpe    , g_cpe    );
    cudaGetSymbolAddress((void**)&p_offin  , g_offin  );
    cudaGetSymbolAddress((void**)&p_h1     , g_h1     );
    cudaGetSymbolAddress((void**)&p_storage, g_storage);
    cudaGetSymbolAddress((void**)&p_kvh    , g_kvh    );
    cudaGetSymbolAddress((void**)&p_sp     , g_sp     );

    cudaFuncSetAttribute(k_attn, cudaFuncAttributeMaxDynamicSharedMemorySize, 67200);

    k_tw2<<<66, 256>>>(hop_w2);
    k_prep<<<BL, 256>>>(x, pos);

    k_gemm_multi_t<<<dim3(64,23), 128>>>(x,
        w_content, b_content, p_content,
        w_val,     b_val,     p_values,
        w_ctx,     b_ctx,     p_ctx,
        sg_w1,     sg_b1,     p_sgh,
        w_cpe,     b_cpe,     p_cpe,
        hop_w1,    hop_b1,    p_h1,
        p_offin);

    k_hop<<<BL, 256>>>(pos, hop_b2, sg_w2, sg_b2);

    k_scan1<<<dim3(BB,16), 256>>>();
    k_scang<<<BB, 32>>>();
    k_scan2<<<dim3(BB,16), 256>>>();

    k_gemm_t<<<dim3(64,4), 128>>>(p_storage, kv_w1, kv_b1, nullptr, p_kvh, 512, 256, 1, 0, 0);
    k_gemm_t<<<dim3(64,1), 128>>>(p_kvh,     kv_w2, kv_b2, nullptr, p_sp,  256, 32,  0, 1, 0);

    k_build2<<<BL, 32>>>();

    k_attn<<<dim3(144, BB, 2), 256, 67200>>>();

    k_ln<<<BL, 256>>>(ln_g, ln_b);
    k_gemm_t<<<dim3(64,4), 128>>>(p_ctx, w_out, b_out, x, out, 256, 256, 0, 0, 1);
}

// round 5
// speedup vs baseline: 5.0369x; 1.0206x over previous
#include <cuda_runtime.h>
#include <math.h>
#include <stdint.h>

#define LL 2048
#define BB 2
#define DD 256
#define PP 32
#define BL (BB*LL)

// ---------------- scratch ----------------
__device__ __align__(256) float g_content[BL*DD];
__device__ __align__(256) float g_values [BL*DD];
__device__ __align__(256) float g_ctx    [BL*DD];   // ctx, later reused as LN output
__device__ __align__(256) float g_sgh    [BL*128];
__device__ __align__(256) float g_gate   [BL];
__device__ __align__(256) float g_gcum   [BL];
__device__ __align__(256) float g_cpe    [BL*PP];
__device__ __align__(256) float g_offin  [BL*288];
__device__ __align__(256) float g_h1     [BL*512];
__device__ __align__(256) float g_Q1     [BL*64];
__device__ __align__(256) float g_K1     [LL*64];
__device__ __align__(256) float g_storage[BL*512];
__device__ __align__(256) float g_kvh    [BL*256];
__device__ __align__(256) float g_sp     [BL*PP];
__device__ __align__(256) float g_Q2     [BL*64];
__device__ __align__(256) float g_K2     [BL*64];
__device__ __align__(256) float g_Vk     [BL*DD];
__device__ __align__(256) float g_csum   [BB*64*256];
__device__ __align__(256) float g_w2bd   [132*512];
__device__ __align__(256) float g_off    [BL*132];
__device__ __align__(256) float g_part   [2u*8u*BL*DD];   // [head][kc][row][col]

__device__ __forceinline__ float gelu_f(float v){
    return 0.5f*v*(1.0f + erff(v*0.70710678118654752f));
}

// ---------------- tf32 helpers ----------------
__device__ __forceinline__ uint32_t f2tf(float f){
    uint32_t u; asm("cvt.rna.tf32.f32 %0, %1;" : "=r"(u) : "f"(f)); return u;
}
__device__ __forceinline__ float f2tf_f(float f){ return __uint_as_float(f2tf(f)); }

__device__ __forceinline__ void mma8(float* c,
        uint32_t a0,uint32_t a1,uint32_t a2,uint32_t a3,
        uint32_t b0,uint32_t b1){
    asm volatile("mma.sync.aligned.m16n8k8.row.col.f32.tf32.tf32.f32 "
        "{%0,%1,%2,%3},{%4,%5,%6,%7},{%8,%9},{%0,%1,%2,%3};"
        : "+f"(c[0]),"+f"(c[1]),"+f"(c[2]),"+f"(c[3])
        : "r"(a0),"r"(a1),"r"(a2),"r"(a3),"r"(b0),"r"(b1));
}

// ---------------- tf32 GEMM core: C = act(A[M,K] @ W[N,K]^T + bias) (+addend) -------
// block 128 thr, BM=64, BN=64, BK=16. Nlim>0 => clamp weight rows / guard stores.
__device__ __forceinline__ void gemm_core(const float* __restrict__ A,
        const float* __restrict__ W, const float* __restrict__ bias,
        const float* __restrict__ addend, float* __restrict__ C,
        int K, int N, int bm, int bn, bool act, int Nlim, bool addres,
        float (*As)[20], float (*Ws)[20]){
    int t = threadIdx.x;
    int w = t>>5, lane = t&31, gr = lane>>2, ct = lane&3;
    int wm = (w&1)*32, wn = (w>>1)*32;
    float acc[2][4][4];
    #pragma unroll
    for (int mt=0;mt<2;mt++)
        #pragma unroll
        for (int nt=0;nt<4;nt++)
            #pragma unroll
            for (int i=0;i<4;i++) acc[mt][nt][i]=0.f;

    for (int k0=0; k0<K; k0+=16){
        #pragma unroll
        for (int i=0;i<2;i++){
            int idx = t + 128*i;
            int r = idx>>2, c4 = (idx&3)*4;
            float4 v = *(const float4*)(A + (size_t)(bm+r)*K + k0 + c4);
            As[r][c4+0]=f2tf_f(v.x); As[r][c4+1]=f2tf_f(v.y);
            As[r][c4+2]=f2tf_f(v.z); As[r][c4+3]=f2tf_f(v.w);
            int grow = bn + r;
            if (Nlim && grow >= Nlim) grow = Nlim-1;
            float4 u = *(const float4*)(W + (size_t)grow*K + k0 + c4);
            Ws[r][c4+0]=f2tf_f(u.x); Ws[r][c4+1]=f2tf_f(u.y);
            Ws[r][c4+2]=f2tf_f(u.z); Ws[r][c4+3]=f2tf_f(u.w);
        }
        __syncthreads();
        #pragma unroll
        for (int k8=0;k8<16;k8+=8){
            uint32_t a[2][4];
            #pragma unroll
            for (int mt=0;mt<2;mt++){
                a[mt][0]=__float_as_uint(As[wm+mt*16+gr  ][k8+ct  ]);
                a[mt][1]=__float_as_uint(As[wm+mt*16+gr+8][k8+ct  ]);
                a[mt][2]=__float_as_uint(As[wm+mt*16+gr  ][k8+ct+4]);
                a[mt][3]=__float_as_uint(As[wm+mt*16+gr+8][k8+ct+4]);
            }
            #pragma unroll
            for (int nt=0;nt<4;nt++){
                uint32_t b0=__float_as_uint(Ws[wn+nt*8+gr][k8+ct  ]);
                uint32_t b1=__float_as_uint(Ws[wn+nt*8+gr][k8+ct+4]);
                #pragma unroll
                for (int mt=0;mt<2;mt++)
                    mma8(acc[mt][nt], a[mt][0],a[mt][1],a[mt][2],a[mt][3], b0,b1);
            }
        }
        __syncthreads();
    }
    #pragma unroll
    for (int mt=0;mt<2;mt++){
        #pragma unroll
        for (int nt=0;nt<4;nt++){
            int col = bn + wn + nt*8 + 2*ct;
            if (Nlim && col >= Nlim) continue;
            int r0 = bm + wm + mt*16 + gr;
            int r1 = r0 + 8;
            float b0v = bias[col], b1v = bias[col+1];
            float v00 = acc[mt][nt][0] + b0v;
            float v01 = acc[mt][nt][1] + b1v;
            float v10 = acc[mt][nt][2] + b0v;
            float v11 = acc[mt][nt][3] + b1v;
            if (act){ v00=gelu_f(v00); v01=gelu_f(v01); v10=gelu_f(v10); v11=gelu_f(v11); }
            if (addres){
                v00 += addend[(size_t)r0*N+col]; v01 += addend[(size_t)r0*N+col+1];
                v10 += addend[(size_t)r1*N+col]; v11 += addend[(size_t)r1*N+col+1];
            }
            C[(size_t)r0*N+col]   = v00;
            C[(size_t)r0*N+col+1] = v01;
            C[(size_t)r1*N+col]   = v10;
            C[(size_t)r1*N+col+1] = v11;
        }
    }
}

// ---------------- merged GEMM: 5 x-projections + hop layer1 (grid.y = 23) ----------------
__global__ __launch_bounds__(128) void k_gemm_multi_t(const float* __restrict__ x,
        const float* __restrict__ w_content, const float* __restrict__ b_content, float* __restrict__ p_content,
        const float* __restrict__ w_val,     const float* __restrict__ b_val,     float* __restrict__ p_values,
        const float* __restrict__ w_ctx,     const float* __restrict__ b_ctx,     float* __restrict__ p_ctx,
        const float* __restrict__ sg_w1,     const float* __restrict__ sg_b1,     float* __restrict__ p_sgh,
        const float* __restrict__ w_cpe,     const float* __restrict__ b_cpe,     float* __restrict__ p_cpe,
        const float* __restrict__ hop_w1,    const float* __restrict__ hop_b1,    float* __restrict__ p_h1,
        const float* __restrict__ p_offin){
    __shared__ float As[64][20];
    __shared__ float Ws[64][20];
    int y = blockIdx.y;
    int seg, bn, N, K, Nlim=0; bool act=false;
    const float* A = x;
    if (y < 12){ seg = y>>2; bn = (y&3)*64; N = 256; K = 256; }
    else if (y < 14){ seg = 3; bn = (y-12)*64; N = 128; K = 256; act = true; }
    else if (y == 14){ seg = 4; bn = 0; N = 32; K = 256; Nlim = 32; }
    else { seg = 5; bn = (y-15)*64; N = 512; K = 288; act = true; A = p_offin; }
    const float* W; const float* Bv; float* C;
    if      (seg==0){ W=w_content; Bv=b_content; C=p_content; }
    else if (seg==1){ W=w_val;     Bv=b_val;     C=p_values;  }
    else if (seg==2){ W=w_ctx;     Bv=b_ctx;     C=p_ctx;     }
    else if (seg==3){ W=sg_w1;     Bv=sg_b1;     C=p_sgh;     }
    else if (seg==4){ W=w_cpe;     Bv=b_cpe;     C=p_cpe;     }
    else            { W=hop_w1;    Bv=hop_b1;    C=p_h1;      }
    gemm_core(A, W, Bv, nullptr, C, K, N, blockIdx.x*64, bn, act, Nlim, false, As, Ws);
}

// ---------------- generic single tf32 GEMM ----------------
__global__ __launch_bounds__(128) void k_gemm_t(const float* __restrict__ A,
        const float* __restrict__ W, const float* __restrict__ bias,
        const float* __restrict__ addend, float* __restrict__ C,
        int K, int N, int act, int Nlim, int addres){
    __shared__ float As[64][20];
    __shared__ float Ws[64][20];
    gemm_core(A, W, bias, addend, C, K, N, blockIdx.x*64, blockIdx.y*64,
              act!=0, Nlim, addres!=0, As, Ws);
}

// ---------------- prep (+ block-diagonal hop_w2 build) ----------------
__global__ __launch_bounds__(256) void k_prep(const float* __restrict__ x,
                                              const float* __restrict__ pos,
                                              const float* __restrict__ hop_w2){
    int row = blockIdx.x; int t = threadIdx.x;
    int b = row >> 11, l = row & 2047;
    float xv = x[(size_t)row*DD + t];
    g_offin[(size_t)row*288 + t]   = xv;
    g_storage[(size_t)row*512 + t] = xv;
    if (t < PP){
        float pp = pos[l*PP + t];
        g_offin[(size_t)row*288 + 256 + t] = pp;
        if (b == 0){
            float s, c; sincosf(pp, &s, &c);
            g_K1[l*64 + t] = c; g_K1[l*64 + 32 + t] = s;
        }
    }
    if (row < 264){                      // 264*256 = 132*512
        int idx = row*256 + t;
        int o = idx >> 9, c = idx & 511;
        int h = o / 33;
        int g = c - (h<<7);
        g_w2bd[idx] = (g >= 0 && g < 128) ? hop_w2[o*128 + g] : 0.f;
    }
}

// ---------------- hop epilogue: off -> coefs/Q1; gate -> Vk ----------------
__global__ __launch_bounds__(256) void k_hop2(const float* __restrict__ pos,
        const float* __restrict__ sg_w2, const float* __restrict__ sg_b2){
    int row = blockIdx.x; int t = threadIdx.x;
    int l = row & 2047;
    __shared__ float offs[132];
    __shared__ float coefs[4];
    __shared__ float wsum[4];
    __shared__ float gateval;
    if (t < 132) offs[t] = g_off[(size_t)row*132 + t];
    float p = (t < 128) ? g_sgh[(size_t)row*128 + t]*sg_w2[t] : 0.f;
    #pragma unroll
    for (int off=16; off>0; off>>=1) p += __shfl_down_sync(0xffffffffu, p, off);
    if ((t&31)==0 && t<128) wsum[t>>5] = p;
    __syncthreads();
    if (t == 0){
        float s = wsum[0]+wsum[1]+wsum[2]+wsum[3];
        float gv = 1.0f/(1.0f+expf(-(s + sg_b2[0])));
        gateval = gv; g_gate[row] = gv;
    }
    if (t >= 32 && t < 36){
        int h = t-32;
        float ww  = 2.0f/(1.0f+expf(-offs[h*33+32])) + 0.1f;
        float w2v = ww*ww + 1e-6f;
        float e1 = expf(-0.5f/w2v);
        float e2 = expf(-2.0f/w2v);
        float totw = 1.0f + 2.0f*e1 + 2.0f*e2;
        coefs[h] = (1.0f + 2.0f*e1*0.9950041652780258f + 2.0f*e2*0.9800665778412416f)
                   / (totw + 1e-6f);
    }
    __syncthreads();
    if (t < PP){
        float pp = pos[l*PP + t];
        float ac=0.f, as=0.f;
        #pragma unroll
        for (int h=0; h<4; h++){
            float th = pp + tanhf(offs[h*33+t])*3.14159265358979323846f;
            float s, c; sincosf(th, &s, &c);
            ac += coefs[h]*c; as += coefs[h]*s;
        }
        const float s0 = 0.04419417382415922f; // 1/(4*sqrt(32))
        g_Q1[(size_t)row*64 + t]      = ac*s0;
        g_Q1[(size_t)row*64 + 32 + t] = as*s0;
    }
    float gv = gateval;
    g_Vk[(size_t)row*DD + t] = g_values[(size_t)row*DD + t]*gv;
}

// ---------------- chunked ctx_avg scan (64 chunks of 32 rows) ----------------
__global__ __launch_bounds__(256) void k_scan1(){ // grid(BB,64)
    int b = blockIdx.x, ch = blockIdx.y, t = threadIdx.x;
    const float* src = g_ctx + ((size_t)(b*2048 + ch*32))*256 + t;
    float s = 0.f;
    #pragma unroll 4
    for (int l=0; l<32; l++) s += src[(size_t)l*256];
    g_csum[(b*64+ch)*256 + t] = s;
}

__global__ __launch_bounds__(256) void k_scan2(){ // grid(BB,64)
    int b = blockIdx.x, ch = blockIdx.y, t = threadIdx.x;
    float run = 0.f;
    for (int j=0; j<ch; j++) run += g_csum[(b*64+j)*256 + t];
    const float* src = g_ctx + ((size_t)(b*2048 + ch*32))*256 + t;
    float* dst = g_storage + ((size_t)(b*2048 + ch*32))*512 + 256 + t;
    int base = ch*32;
    #pragma unroll 4
    for (int l=0; l<32; l++){
        run += src[(size_t)l*256];
        dst[(size_t)l*512] = run / (float)(base + l + 1);
    }
}

__global__ void k_scang(){ // grid(BB), 32 thr
    int b = blockIdx.x, lane = threadIdx.x;
    float carry = 0.f;
    for (int l0=0; l0<LL; l0+=32){
        float v = g_gate[b*LL + l0 + lane];
        #pragma unroll
        for (int o=1;o<32;o<<=1){
            float n = __shfl_up_sync(0xffffffffu, v, o);
            if (lane >= o) v += n;
        }
        float tot = __shfl_sync(0xffffffffu, v, 31);
        g_gcum[b*LL + l0 + lane] = fmaxf(v + carry, 1.0f);
        carry += tot;
    }
}

// ---------------- Q2/K2 ----------------
__global__ void k_build2(){
    int row = blockIdx.x; int t = threadIdx.x; // 32 threads
    const float PIf = 3.14159265358979323846f;
    float spv = tanhf(g_sp[(size_t)row*PP + t])*PIf;
    float s, c; sincosf(spv, &s, &c);
    g_K2[(size_t)row*64 + t]      = c;
    g_K2[(size_t)row*64 + 32 + t] = s;
    float kp  = tanhf(g_cpe[(size_t)row*PP + t])*PIf;
    float inv = rsqrtf(g_gcum[row]) * 0.1767766952966369f; // 1/sqrt(32)
    sincosf(kp, &s, &c);
    g_Q2[(size_t)row*64 + t]      = c*inv;
    g_Q2[(size_t)row*64 + 32 + t] = s*inv;
}

// ---------------- split-KV causal attention (tf32 mma) ----------------
__global__ __launch_bounds__(256) void k_attn(){
    int head = blockIdx.z, b = blockIdx.y;
    int id = blockIdx.x;                    // 0..143
    int g = 0;
    while (id >= 2*(g+1)*(g+2)) g++;
    int e  = id - 2*g*(g+1);
    int qt = 4*g + e/(g+1);
    int kc = e - (e/(g+1))*(g+1);
    int kt0 = kc*8;
    int ktend = 2*qt + 2; if (ktend > kt0+8) ktend = kt0+8;

    extern __shared__ float sm[];
    float* Qs = sm;              // [64][65]
    float* Ks = sm + 4160;       // [32][65]
    float* Ss = sm + 6240;       // [64][33]
    float* Vs = sm + 8352;       // [32][264]

    const float* Q  = head ? g_Q2 + (size_t)b*LL*64 : g_Q1 + (size_t)b*LL*64;
    const float* Kp = head ? g_K2 + (size_t)b*LL*64 : g_K1;
    const float* V  = head ? g_Vk + (size_t)b*LL*DD : g_content + (size_t)b*LL*DD;

    int t = threadIdx.x;
    int w = t>>5, lane = t&31, gr = lane>>2, ct = lane&3;

    const float* Qt = Q + (size_t)qt*64*64;
    for (int idx=t; idx<4096; idx+=256)
        Qs[(idx>>6)*65 + (idx&63)] = f2tf_f(Qt[idx]);

    float acc[16][4];
    #pragma unroll
    for (int i=0;i<16;i++){ acc[i][0]=0.f; acc[i][1]=0.f; acc[i][2]=0.f; acc[i][3]=0.f; }

    int wmS = (w&3)*16, wnS = (w>>2)*16;
    int wmP = (w&3)*16, wnP = (w>>2)*128;

    for (int kt=kt0; kt<ktend; kt++){
        __syncthreads();
        const float* Kt = Kp + (size_t)kt*32*64;
        for (int idx=t; idx<2048; idx+=256)
            Ks[(idx>>6)*65 + (idx&63)] = f2tf_f(Kt[idx]);
        const float4* Vt4 = (const float4*)(V + (size_t)kt*32*DD);
        for (int idx=t; idx<2048; idx+=256){
            int r = idx>>6, c4 = idx&63;
            float4 v = Vt4[idx];
            float* d = Vs + r*264 + c4*4;
            d[0]=f2tf_f(v.x); d[1]=f2tf_f(v.y); d[2]=f2tf_f(v.z); d[3]=f2tf_f(v.w);
        }
        __syncthreads();
        // ---- S = Q @ K^T (64x32, K=64) ----
        float cS[2][4];
        #pragma unroll
        for (int nt=0;nt<2;nt++){ cS[nt][0]=0.f; cS[nt][1]=0.f; cS[nt][2]=0.f; cS[nt][3]=0.f; }
        #pragma unroll
        for (int k8=0;k8<64;k8+=8){
            uint32_t a0=__float_as_uint(Qs[(wmS+gr  )*65 + k8+ct  ]);
            uint32_t a1=__float_as_uint(Qs[(wmS+gr+8)*65 + k8+ct  ]);
            uint32_t a2=__float_as_uint(Qs[(wmS+gr  )*65 + k8+ct+4]);
            uint32_t a3=__float_as_uint(Qs[(wmS+gr+8)*65 + k8+ct+4]);
            #pragma unroll
            for (int nt=0;nt<2;nt++){
                uint32_t b0=__float_as_uint(Ks[(wnS+nt*8+gr)*65 + k8+ct  ]);
                uint32_t b1=__float_as_uint(Ks[(wnS+nt*8+gr)*65 + k8+ct+4]);
                mma8(cS[nt], a0,a1,a2,a3, b0,b1);
            }
        }
        bool diag = (kt >= 2*qt);
        #pragma unroll
        for (int nt=0;nt<2;nt++){
            int col0 = wnS + nt*8 + 2*ct;
            int r0 = wmS + gr, r1 = r0 + 8;
            float v00=cS[nt][0], v01=cS[nt][1], v10=cS[nt][2], v11=cS[nt][3];
            if (diag){
                int gcol = kt*32 + col0;
                int grow0 = qt*64 + r0, grow1 = qt*64 + r1;
                if (gcol   > grow0) v00 = 0.f;
                if (gcol+1 > grow0) v01 = 0.f;
                if (gcol   > grow1) v10 = 0.f;
                if (gcol+1 > grow1) v11 = 0.f;
            }
            Ss[r0*33+col0]   = f2tf_f(v00);
            Ss[r0*33+col0+1] = f2tf_f(v01);
            Ss[r1*33+col0]   = f2tf_f(v10);
            Ss[r1*33+col0+1] = f2tf_f(v11);
        }
        __syncthreads();
        // ---- acc += S @ V (64x256, K=32) ----
        #pragma unroll
        for (int k8=0;k8<32;k8+=8){
            uint32_t a0=__float_as_uint(Ss[(wmP+gr  )*33 + k8+ct  ]);
            uint32_t a1=__float_as_uint(Ss[(wmP+gr+8)*33 + k8+ct  ]);
            uint32_t a2=__float_as_uint(Ss[(wmP+gr  )*33 + k8+ct+4]);
            uint32_t a3=__float_as_uint(Ss[(wmP+gr+8)*33 + k8+ct+4]);
            #pragma unroll
            for (int nt=0;nt<16;nt++){
                uint32_t b0=__float_as_uint(Vs[(k8+ct  )*264 + wnP + nt*8 + gr]);
                uint32_t b1=__float_as_uint(Vs[(k8+ct+4)*264 + wnP + nt*8 + gr]);
                mma8(acc[nt], a0,a1,a2,a3, b0,b1);
            }
        }
    }
    float* P = g_part + (((size_t)(head*8 + kc))*BL + (size_t)b*2048 + (size_t)qt*64)*256;
    #pragma unroll
    for (int nt=0;nt<16;nt++){
        int col = wnP + nt*8 + 2*ct;
        int r0 = wmP + gr, r1 = r0 + 8;
        *(float2*)(P + (size_t)r0*256 + col) = make_float2(acc[nt][0], acc[nt][1]);
        *(float2*)(P + (size_t)r1*256 + col) = make_float2(acc[nt][2], acc[nt][3]);
    }
}

// ---------------- layernorm (sums partials) ----------------
__global__ __launch_bounds__(256) void k_ln(const float* __restrict__ lng,
                                            const float* __restrict__ lnb){
    int row = blockIdx.x, t = threadIdx.x;
    int l = row & 2047;
    int nch = ((l >> 6) >> 2) + 1;
    float c = 0.f;
    for (int kc=0; kc<nch; kc++){
        c += g_part[(((size_t)kc)*BL + row)*256 + t];
        c += g_part[(((size_t)(8+kc))*BL + row)*256 + t];
    }
    float s = c, q = c*c;
    #pragma unroll
    for (int o=16;o>0;o>>=1){
        s += __shfl_down_sync(0xffffffffu, s, o);
        q += __shfl_down_sync(0xffffffffu, q, o);
    }
    __shared__ float ws[8], wq[8];
    __shared__ float mu_s, inv_s;
    if ((t&31)==0){ ws[t>>5]=s; wq[t>>5]=q; }
    __syncthreads();
    if (t==0){
        float S=0.f, Qq=0.f;
        #pragma unroll
        for (int i=0;i<8;i++){ S+=ws[i]; Qq+=wq[i]; }
        float mu = S*(1.0f/256.0f);
        float var = Qq*(1.0f/256.0f) - mu*mu;
        mu_s = mu; inv_s = rsqrtf(var + 1e-5f);
    }
    __syncthreads();
    float v = (c - mu_s)*inv_s*lng[t] + lnb[t];
    g_ctx[(size_t)row*DD + t] = v;
}

// ---------------- launch ----------------
extern "C" void kernel_launch(void* const* d_in, const int* in_sizes, int n_in,
                              void* d_out, int out_size){
    const float* x         = (const float*)d_in[0];
    const float* pos       = (const float*)d_in[1];
    const float* w_content = (const float*)d_in[2];
    const float* b_content = (const float*)d_in[3];
    const float* hop_w1    = (const float*)d_in[4];
    const float* hop_b1    = (const float*)d_in[5];
    const float* hop_w2    = (const float*)d_in[6];
    const float* hop_b2    = (const float*)d_in[7];
    const float* w_cpe     = (const float*)d_in[8];
    const float* b_cpe     = (const float*)d_in[9];
    const float* w_val     = (const float*)d_in[10];
    const float* b_val     = (const float*)d_in[11];
    const float* w_ctx     = (const float*)d_in[12];
    const float* b_ctx     = (const float*)d_in[13];
    const float* kv_w1     = (const float*)d_in[14];
    const float* kv_b1     = (const float*)d_in[15];
    const float* kv_w2     = (const float*)d_in[16];
    const float* kv_b2     = (const float*)d_in[17];
    const float* sg_w1     = (const float*)d_in[18];
    const float* sg_b1     = (const float*)d_in[19];
    const float* sg_w2     = (const float*)d_in[20];
    const float* sg_b2     = (const float*)d_in[21];
    const float* ln_g      = (const float*)d_in[22];
    const float* ln_b      = (const float*)d_in[23];
    const float* w_out     = (const float*)d_in[24];
    const float* b_out     = (const float*)d_in[25];
    float* out = (float*)d_out;

    float *p_content, *p_values, *p_ctx, *p_sgh, *p_cpe, *p_offin, *p_h1,
          *p_storage, *p_kvh, *p_sp, *p_w2bd, *p_off;
    cudaGetSymbolAddress((void**)&p_content, g_content);
    cudaGetSymbolAddress((void**)&p_values , g_values );
    cudaGetSymbolAddress((void**)&p_ctx    , g_ctx    );
    cudaGetSymbolAddress((void**)&p_sgh    , g_sgh    );
    cudaGetSymbolAddress((void**)&p_cpe    , g_cpe    );
    cudaGetSymbolAddress((void**)&p_offin  , g_offin  );
    cudaGetSymbolAddress((void**)&p_h1     , g_h1     );
    cudaGetSymbolAddress((void**)&p_storage, g_storage);
    cudaGetSymbolAddress((void**)&p_kvh    , g_kvh    );
    cudaGetSymbolAddress((void**)&p_sp     , g_sp     );
    cudaGetSymbolAddress((void**)&p_w2bd   , g_w2bd   );
    cudaGetSymbolAddress((void**)&p_off    , g_off    );

    cudaFuncSetAttribute(k_attn, cudaFuncAttributeMaxDynamicSharedMemorySize, 67200);

    k_prep<<<BL, 256>>>(x, pos, hop_w2);

    k_gemm_multi_t<<<dim3(64,23), 128>>>(x,
        w_content, b_content, p_content,
        w_val,     b_val,     p_values,
        w_ctx,     b_ctx,     p_ctx,
        sg_w1,     sg_b1,     p_sgh,
        w_cpe,     b_cpe,     p_cpe,
        hop_w1,    hop_b1,    p_h1,
        p_offin);

    // hop layer 2 as block-diagonal GEMM: off = h1 @ W2bd^T  (M=4096, N=132, K=512)
    k_gemm_t<<<dim3(64,3), 128>>>(p_h1, p_w2bd, hop_b2, nullptr, p_off, 512, 132, 0, 132, 0);

    k_hop2<<<BL, 256>>>(pos, sg_w2, sg_b2);

    k_scan1<<<dim3(BB,64), 256>>>();
    k_scang<<<BB, 32>>>();
    k_scan2<<<dim3(BB,64), 256>>>();

    k_gemm_t<<<dim3(64,4), 128>>>(p_storage, kv_w1, kv_b1, nullptr, p_kvh, 512, 256, 1, 0, 0);
    k_gemm_t<<<dim3(64,1), 128>>>(p_kvh,     kv_w2, kv_b2, nullptr, p_sp,  256, 32,  0, 32, 0);

    k_build2<<<BL, 32>>>();

    k_attn<<<dim3(144, BB, 2), 256, 67200>>>();

    k_ln<<<BL, 256>>>(ln_g, ln_b);
    k_gemm_t<<<dim3(64,4), 128>>>(p_ctx, w_out, b_out, x, out, 256, 256, 0, 0, 1);
}

// round 6
// speedup vs baseline: 6.3022x; 1.2512x over previous
#include <cuda_runtime.h>
#include <math.h>
#include <stdint.h>

#define LL 2048
#define BB 2
#define DD 256
#define PP 32
#define BL (BB*LL)

// ---------------- scratch ----------------
__device__ __align__(256) float g_content[BL*DD];
__device__ __align__(256) float g_values [BL*DD];
__device__ __align__(256) float g_ctx    [BL*DD];
__device__ __align__(256) float g_sgh    [BL*128];
__device__ __align__(256) float g_gate   [BL];
__device__ __align__(256) float g_gcum   [BL];
__device__ __align__(256) float g_cpe    [BL*PP];
__device__ __align__(256) float g_offin  [BL*288];
__device__ __align__(256) float g_h1     [BL*512];
__device__ __align__(256) float g_Q1     [BL*64];
__device__ __align__(256) float g_K1     [LL*64];
__device__ __align__(256) float g_storage[BL*512];
__device__ __align__(256) float g_kvh    [BL*256];
__device__ __align__(256) float g_sp     [BL*PP];
__device__ __align__(256) float g_Q2     [BL*64];
__device__ __align__(256) float g_K2     [BL*64];
__device__ __align__(256) float g_Vk     [BL*DD];
__device__ __align__(256) float g_csum   [BB*64*256];
__device__ __align__(256) float g_w2bd   [132*512];
__device__ __align__(256) float g_off    [BL*132];
__device__ __align__(256) float g_part   [2u*8u*BL*DD];   // [head][kc][row][col]

__device__ __forceinline__ float gelu_f(float v){
    return 0.5f*v*(1.0f + erff(v*0.70710678118654752f));
}

// ---------------- tf32 / async helpers ----------------
__device__ __forceinline__ uint32_t f2tf(float f){
    uint32_t u; asm("cvt.rna.tf32.f32 %0, %1;" : "=r"(u) : "f"(f)); return u;
}
__device__ __forceinline__ float f2tf_f(float f){ return __uint_as_float(f2tf(f)); }

__device__ __forceinline__ void mma8(float* c,
        uint32_t a0,uint32_t a1,uint32_t a2,uint32_t a3,
        uint32_t b0,uint32_t b1){
    asm volatile("mma.sync.aligned.m16n8k8.row.col.f32.tf32.tf32.f32 "
        "{%0,%1,%2,%3},{%4,%5,%6,%7},{%8,%9},{%0,%1,%2,%3};"
        : "+f"(c[0]),"+f"(c[1]),"+f"(c[2]),"+f"(c[3])
        : "r"(a0),"r"(a1),"r"(a2),"r"(a3),"r"(b0),"r"(b1));
}

__device__ __forceinline__ void cpasync16(void* s, const void* g){
    uint32_t sa = (uint32_t)__cvta_generic_to_shared(s);
    asm volatile("cp.async.cg.shared.global [%0], [%1], 16;" :: "r"(sa), "l"(g));
}
__device__ __forceinline__ void cp_commit(){ asm volatile("cp.async.commit_group;"); }
__device__ __forceinline__ void cp_wait0(){ asm volatile("cp.async.wait_group 0;" ::: "memory"); }

// ---------------- tf32 GEMM core (register-prefetch pipelined) ----------------
__device__ __forceinline__ void gemm_core(const float* __restrict__ A,
        const float* __restrict__ W, const float* __restrict__ bias,
        const float* __restrict__ addend, float* __restrict__ C,
        int K, int N, int bm, int bn, bool act, int Nlim, bool addres,
        float (*As)[20], float (*Ws)[20]){
    int t = threadIdx.x;
    int w = t>>5, lane = t&31, gr = lane>>2, ct = lane&3;
    int wm = (w&1)*32, wn = (w>>1)*32;
    int r0 = t>>2, c4 = (t&3)*4;
    float acc[2][4][4];
    #pragma unroll
    for (int mt=0;mt<2;mt++)
        #pragma unroll
        for (int nt=0;nt<4;nt++)
            #pragma unroll
            for (int i=0;i<4;i++) acc[mt][nt][i]=0.f;

    float4 pa0, pa1, pw0, pw1;
    int g0 = bn+r0, g1 = bn+r0+32;
    if (Nlim){ if (g0>=Nlim) g0=Nlim-1; if (g1>=Nlim) g1=Nlim-1; }
    const float* Ar0 = A + (size_t)(bm+r0)*K + c4;
    const float* Ar1 = A + (size_t)(bm+r0+32)*K + c4;
    const float* Wr0 = W + (size_t)g0*K + c4;
    const float* Wr1 = W + (size_t)g1*K + c4;
    pa0 = *(const float4*)Ar0; pa1 = *(const float4*)Ar1;
    pw0 = *(const float4*)Wr0; pw1 = *(const float4*)Wr1;

    for (int k0=0; k0<K; k0+=16){
        As[r0   ][c4+0]=f2tf_f(pa0.x); As[r0   ][c4+1]=f2tf_f(pa0.y);
        As[r0   ][c4+2]=f2tf_f(pa0.z); As[r0   ][c4+3]=f2tf_f(pa0.w);
        As[r0+32][c4+0]=f2tf_f(pa1.x); As[r0+32][c4+1]=f2tf_f(pa1.y);
        As[r0+32][c4+2]=f2tf_f(pa1.z); As[r0+32][c4+3]=f2tf_f(pa1.w);
        Ws[r0   ][c4+0]=f2tf_f(pw0.x); Ws[r0   ][c4+1]=f2tf_f(pw0.y);
        Ws[r0   ][c4+2]=f2tf_f(pw0.z); Ws[r0   ][c4+3]=f2tf_f(pw0.w);
        Ws[r0+32][c4+0]=f2tf_f(pw1.x); Ws[r0+32][c4+1]=f2tf_f(pw1.y);
        Ws[r0+32][c4+2]=f2tf_f(pw1.z); Ws[r0+32][c4+3]=f2tf_f(pw1.w);
        __syncthreads();
        if (k0+16 < K){
            pa0 = *(const float4*)(Ar0 + k0+16); pa1 = *(const float4*)(Ar1 + k0+16);
            pw0 = *(const float4*)(Wr0 + k0+16); pw1 = *(const float4*)(Wr1 + k0+16);
        }
        #pragma unroll
        for (int k8=0;k8<16;k8+=8){
            uint32_t a[2][4];
            #pragma unroll
            for (int mt=0;mt<2;mt++){
                a[mt][0]=__float_as_uint(As[wm+mt*16+gr  ][k8+ct  ]);
                a[mt][1]=__float_as_uint(As[wm+mt*16+gr+8][k8+ct  ]);
                a[mt][2]=__float_as_uint(As[wm+mt*16+gr  ][k8+ct+4]);
                a[mt][3]=__float_as_uint(As[wm+mt*16+gr+8][k8+ct+4]);
            }
            #pragma unroll
            for (int nt=0;nt<4;nt++){
                uint32_t b0=__float_as_uint(Ws[wn+nt*8+gr][k8+ct  ]);
                uint32_t b1=__float_as_uint(Ws[wn+nt*8+gr][k8+ct+4]);
                #pragma unroll
                for (int mt=0;mt<2;mt++)
                    mma8(acc[mt][nt], a[mt][0],a[mt][1],a[mt][2],a[mt][3], b0,b1);
            }
        }
        __syncthreads();
    }
    #pragma unroll
    for (int mt=0;mt<2;mt++){
        #pragma unroll
        for (int nt=0;nt<4;nt++){
            int col = bn + wn + nt*8 + 2*ct;
            if (Nlim && col >= Nlim) continue;
            int rr0 = bm + wm + mt*16 + gr;
            int rr1 = rr0 + 8;
            float b0v = bias[col], b1v = bias[col+1];
            float v00 = acc[mt][nt][0] + b0v;
            float v01 = acc[mt][nt][1] + b1v;
            float v10 = acc[mt][nt][2] + b0v;
            float v11 = acc[mt][nt][3] + b1v;
            if (act){ v00=gelu_f(v00); v01=gelu_f(v01); v10=gelu_f(v10); v11=gelu_f(v11); }
            if (addres){
                v00 += addend[(size_t)rr0*N+col]; v01 += addend[(size_t)rr0*N+col+1];
                v10 += addend[(size_t)rr1*N+col]; v11 += addend[(size_t)rr1*N+col+1];
            }
            C[(size_t)rr0*N+col]   = v00;
            C[(size_t)rr0*N+col+1] = v01;
            C[(size_t)rr1*N+col]   = v10;
            C[(size_t)rr1*N+col+1] = v11;
        }
    }
}

// ---------------- merged GEMM: 5 x-projections + hop layer1 (grid.y = 23) ----------------
__global__ __launch_bounds__(128) void k_gemm_multi_t(const float* __restrict__ x,
        const float* __restrict__ w_content, const float* __restrict__ b_content, float* __restrict__ p_content,
        const float* __restrict__ w_val,     const float* __restrict__ b_val,     float* __restrict__ p_values,
        const float* __restrict__ w_ctx,     const float* __restrict__ b_ctx,     float* __restrict__ p_ctx,
        const float* __restrict__ sg_w1,     const float* __restrict__ sg_b1,     float* __restrict__ p_sgh,
        const float* __restrict__ w_cpe,     const float* __restrict__ b_cpe,     float* __restrict__ p_cpe,
        const float* __restrict__ hop_w1,    const float* __restrict__ hop_b1,    float* __restrict__ p_h1,
        const float* __restrict__ p_offin){
    __shared__ float As[64][20];
    __shared__ float Ws[64][20];
    int y = blockIdx.y;
    int seg, bn, N, K, Nlim=0; bool act=false;
    const float* A = x;
    if (y < 12){ seg = y>>2; bn = (y&3)*64; N = 256; K = 256; }
    else if (y < 14){ seg = 3; bn = (y-12)*64; N = 128; K = 256; act = true; }
    else if (y == 14){ seg = 4; bn = 0; N = 32; K = 256; Nlim = 32; }
    else { seg = 5; bn = (y-15)*64; N = 512; K = 288; act = true; A = p_offin; }
    const float* W; const float* Bv; float* C;
    if      (seg==0){ W=w_content; Bv=b_content; C=p_content; }
    else if (seg==1){ W=w_val;     Bv=b_val;     C=p_values;  }
    else if (seg==2){ W=w_ctx;     Bv=b_ctx;     C=p_ctx;     }
    else if (seg==3){ W=sg_w1;     Bv=sg_b1;     C=p_sgh;     }
    else if (seg==4){ W=w_cpe;     Bv=b_cpe;     C=p_cpe;     }
    else            { W=hop_w1;    Bv=hop_b1;    C=p_h1;      }
    gemm_core(A, W, Bv, nullptr, C, K, N, blockIdx.x*64, bn, act, Nlim, false, As, Ws);
}

// ---------------- generic single tf32 GEMM ----------------
__global__ __launch_bounds__(128) void k_gemm_t(const float* __restrict__ A,
        const float* __restrict__ W, const float* __restrict__ bias,
        const float* __restrict__ addend, float* __restrict__ C,
        int K, int N, int act, int Nlim, int addres){
    __shared__ float As[64][20];
    __shared__ float Ws[64][20];
    gemm_core(A, W, bias, addend, C, K, N, blockIdx.x*64, blockIdx.y*64,
              act!=0, Nlim, addres!=0, As, Ws);
}

// ---------------- prep (+ block-diagonal hop_w2 build) ----------------
__global__ __launch_bounds__(256) void k_prep(const float* __restrict__ x,
                                              const float* __restrict__ pos,
                                              const float* __restrict__ hop_w2){
    int row = blockIdx.x; int t = threadIdx.x;
    int b = row >> 11, l = row & 2047;
    float xv = x[(size_t)row*DD + t];
    g_offin[(size_t)row*288 + t]   = xv;
    g_storage[(size_t)row*512 + t] = xv;
    if (t < PP){
        float pp = pos[l*PP + t];
        g_offin[(size_t)row*288 + 256 + t] = pp;
        if (b == 0){
            float s, c; sincosf(pp, &s, &c);
            g_K1[l*64 + t] = c; g_K1[l*64 + 32 + t] = s;
        }
    }
    if (row < 264){                      // 264*256 = 132*512
        int idx = row*256 + t;
        int o = idx >> 9, c = idx & 511;
        int h = o / 33;
        int g = c - (h<<7);
        g_w2bd[idx] = (g >= 0 && g < 128) ? hop_w2[o*128 + g] : 0.f;
    }
}

// ---------------- hop epilogue: off -> coefs/Q1; gate -> Vk ----------------
__global__ __launch_bounds__(256) void k_hop2(const float* __restrict__ pos,
        const float* __restrict__ sg_w2, const float* __restrict__ sg_b2){
    int row = blockIdx.x; int t = threadIdx.x;
    int l = row & 2047;
    __shared__ float offs[132];
    __shared__ float coefs[4];
    __shared__ float wsum[4];
    __shared__ float gateval;
    if (t < 132) offs[t] = g_off[(size_t)row*132 + t];
    float p = (t < 128) ? g_sgh[(size_t)row*128 + t]*sg_w2[t] : 0.f;
    #pragma unroll
    for (int off=16; off>0; off>>=1) p += __shfl_down_sync(0xffffffffu, p, off);
    if ((t&31)==0 && t<128) wsum[t>>5] = p;
    __syncthreads();
    if (t == 0){
        float s = wsum[0]+wsum[1]+wsum[2]+wsum[3];
        float gv = 1.0f/(1.0f+expf(-(s + sg_b2[0])));
        gateval = gv; g_gate[row] = gv;
    }
    if (t >= 32 && t < 36){
        int h = t-32;
        float ww  = 2.0f/(1.0f+expf(-offs[h*33+32])) + 0.1f;
        float w2v = ww*ww + 1e-6f;
        float e1 = expf(-0.5f/w2v);
        float e2 = expf(-2.0f/w2v);
        float totw = 1.0f + 2.0f*e1 + 2.0f*e2;
        coefs[h] = (1.0f + 2.0f*e1*0.9950041652780258f + 2.0f*e2*0.9800665778412416f)
                   / (totw + 1e-6f);
    }
    __syncthreads();
    if (t < PP){
        float pp = pos[l*PP + t];
        float ac=0.f, as=0.f;
        #pragma unroll
        for (int h=0; h<4; h++){
            float th = pp + tanhf(offs[h*33+t])*3.14159265358979323846f;
            float s, c; sincosf(th, &s, &c);
            ac += coefs[h]*c; as += coefs[h]*s;
        }
        const float s0 = 0.04419417382415922f; // 1/(4*sqrt(32))
        g_Q1[(size_t)row*64 + t]      = ac*s0;
        g_Q1[(size_t)row*64 + 32 + t] = as*s0;
    }
    float gv = gateval;
    g_Vk[(size_t)row*DD + t] = g_values[(size_t)row*DD + t]*gv;
}

// ---------------- chunked ctx_avg scan (64 chunks of 32 rows) ----------------
__global__ __launch_bounds__(256) void k_scan1(){ // grid(BB,64)
    int b = blockIdx.x, ch = blockIdx.y, t = threadIdx.x;
    const float* src = g_ctx + ((size_t)(b*2048 + ch*32))*256 + t;
    float s = 0.f;
    #pragma unroll 4
    for (int l=0; l<32; l++) s += src[(size_t)l*256];
    g_csum[(b*64+ch)*256 + t] = s;
}

__global__ __launch_bounds__(256) void k_scan2(){ // grid(BB,64)
    int b = blockIdx.x, ch = blockIdx.y, t = threadIdx.x;
    float run = 0.f;
    for (int j=0; j<ch; j++) run += g_csum[(b*64+j)*256 + t];
    const float* src = g_ctx + ((size_t)(b*2048 + ch*32))*256 + t;
    float* dst = g_storage + ((size_t)(b*2048 + ch*32))*512 + 256 + t;
    int base = ch*32;
    #pragma unroll 4
    for (int l=0; l<32; l++){
        run += src[(size_t)l*256];
        dst[(size_t)l*512] = run / (float)(base + l + 1);
    }
}

__global__ void k_scang(){ // grid(BB), 32 thr
    int b = blockIdx.x, lane = threadIdx.x;
    float carry = 0.f;
    for (int l0=0; l0<LL; l0+=32){
        float v = g_gate[b*LL + l0 + lane];
        #pragma unroll
        for (int o=1;o<32;o<<=1){
            float n = __shfl_up_sync(0xffffffffu, v, o);
            if (lane >= o) v += n;
        }
        float tot = __shfl_sync(0xffffffffu, v, 31);
        g_gcum[b*LL + l0 + lane] = fmaxf(v + carry, 1.0f);
        carry += tot;
    }
}

// ---------------- Q2/K2 (8 rows per block) ----------------
__global__ __launch_bounds__(256) void k_build2(){
    int row = blockIdx.x*8 + (threadIdx.x>>5);
    int t = threadIdx.x&31;
    const float PIf = 3.14159265358979323846f;
    float spv = tanhf(g_sp[(size_t)row*PP + t])*PIf;
    float s, c; sincosf(spv, &s, &c);
    g_K2[(size_t)row*64 + t]      = c;
    g_K2[(size_t)row*64 + 32 + t] = s;
    float kp  = tanhf(g_cpe[(size_t)row*PP + t])*PIf;
    float inv = rsqrtf(g_gcum[row]) * 0.1767766952966369f; // 1/sqrt(32)
    sincosf(kp, &s, &c);
    g_Q2[(size_t)row*64 + t]      = c*inv;
    g_Q2[(size_t)row*64 + 32 + t] = s*inv;
}

// ---------------- split-KV causal attention (tf32 mma, cp.async double-buffered) ------
// smem floats: Qs[64*68]=4352, Ss[64*36]=2304, Kb[2][32*68]=4352, Vb[2][32*264]=16896
#define ATTN_SMEM_FLOATS (4352+2304+4352+16896)
__global__ __launch_bounds__(256,2) void k_attn(){
    int head = blockIdx.z, b = blockIdx.y;
    int id = blockIdx.x;                    // 0..143
    int g = 0;
    while (id >= 2*(g+1)*(g+2)) g++;
    int e  = id - 2*g*(g+1);
    int qt = 4*g + e/(g+1);
    int kc = e - (e/(g+1))*(g+1);
    int kt0 = kc*8;
    int ktend = 2*qt + 2; if (ktend > kt0+8) ktend = kt0+8;

    extern __shared__ float sm[];
    float* Qs  = sm;                    // [64][68]
    float* Ss  = sm + 4352;             // [64][36]
    float* Kb0 = sm + 6656;             // [32][68]
    float* Kb1 = sm + 8832;
    float* Vb0 = sm + 11008;            // [32][264]
    float* Vb1 = sm + 19456;

    const float* Q  = head ? g_Q2 + (size_t)b*LL*64 : g_Q1 + (size_t)b*LL*64;
    const float* Kp = head ? g_K2 + (size_t)b*LL*64 : g_K1;
    const float* V  = head ? g_Vk + (size_t)b*LL*DD : g_content + (size_t)b*LL*DD;

    int t = threadIdx.x;
    int w = t>>5, lane = t&31, gr = lane>>2, ct = lane&3;

    // issue async loads for first tile
    {
        const float* Kt = Kp + (size_t)kt0*2048;
        const float* Vt = V  + (size_t)kt0*8192;
        #pragma unroll
        for (int i=0;i<2;i++){
            int c = t*2+i; int r=c>>4, c4=(c&15)*4;
            cpasync16(Kb0 + r*68 + c4, Kt + r*64 + c4);
        }
        #pragma unroll
        for (int i=0;i<8;i++){
            int c = t + 256*i; int r=c>>6, c4=(c&63)*4;
            cpasync16(Vb0 + r*264 + c4, Vt + r*256 + c4);
        }
        cp_commit();
    }

    // load Q tile (overlaps with async)
    const float* Qt = Q + (size_t)qt*64*64;
    for (int idx=t; idx<4096; idx+=256)
        Qs[(idx>>6)*68 + (idx&63)] = f2tf_f(Qt[idx]);

    float acc[16][4];
    #pragma unroll
    for (int i=0;i<16;i++){ acc[i][0]=0.f; acc[i][1]=0.f; acc[i][2]=0.f; acc[i][3]=0.f; }

    int wmS = (w&3)*16, wnS = (w>>2)*16;
    int wmP = (w&3)*16, wnP = (w>>2)*128;
    int buf = 0;

    for (int kt=kt0; kt<ktend; kt++, buf^=1){
        cp_wait0();
        __syncthreads();
        if (kt+1 < ktend){
            float* Kd = buf ? Kb0 : Kb1;
            float* Vd = buf ? Vb0 : Vb1;
            const float* Kt = Kp + (size_t)(kt+1)*2048;
            const float* Vt = V  + (size_t)(kt+1)*8192;
            #pragma unroll
            for (int i=0;i<2;i++){
                int c = t*2+i; int r=c>>4, c4=(c&15)*4;
                cpasync16(Kd + r*68 + c4, Kt + r*64 + c4);
            }
            #pragma unroll
            for (int i=0;i<8;i++){
                int c = t + 256*i; int r=c>>6, c4=(c&63)*4;
                cpasync16(Vd + r*264 + c4, Vt + r*256 + c4);
            }
            cp_commit();
        }
        const float* Ks = buf ? Kb1 : Kb0;
        const float* Vs = buf ? Vb1 : Vb0;
        // ---- S = Q @ K^T (64x32, K=64) ----
        float cS[2][4];
        #pragma unroll
        for (int nt=0;nt<2;nt++){ cS[nt][0]=0.f; cS[nt][1]=0.f; cS[nt][2]=0.f; cS[nt][3]=0.f; }
        #pragma unroll
        for (int k8=0;k8<64;k8+=8){
            uint32_t a0=__float_as_uint(Qs[(wmS+gr  )*68 + k8+ct  ]);
            uint32_t a1=__float_as_uint(Qs[(wmS+gr+8)*68 + k8+ct  ]);
            uint32_t a2=__float_as_uint(Qs[(wmS+gr  )*68 + k8+ct+4]);
            uint32_t a3=__float_as_uint(Qs[(wmS+gr+8)*68 + k8+ct+4]);
            #pragma unroll
            for (int nt=0;nt<2;nt++){
                uint32_t b0=f2tf(Ks[(wnS+nt*8+gr)*68 + k8+ct  ]);
                uint32_t b1=f2tf(Ks[(wnS+nt*8+gr)*68 + k8+ct+4]);
                mma8(cS[nt], a0,a1,a2,a3, b0,b1);
            }
        }
        bool diag = (kt >= 2*qt);
        #pragma unroll
        for (int nt=0;nt<2;nt++){
            int col0 = wnS + nt*8 + 2*ct;
            int r0 = wmS + gr, r1 = r0 + 8;
            float v00=cS[nt][0], v01=cS[nt][1], v10=cS[nt][2], v11=cS[nt][3];
            if (diag){
                int gcol = kt*32 + col0;
                int grow0 = qt*64 + r0, grow1 = qt*64 + r1;
                if (gcol   > grow0) v00 = 0.f;
                if (gcol+1 > grow0) v01 = 0.f;
                if (gcol   > grow1) v10 = 0.f;
                if (gcol+1 > grow1) v11 = 0.f;
            }
            Ss[r0*36+col0]   = f2tf_f(v00);
            Ss[r0*36+col0+1] = f2tf_f(v01);
            Ss[r1*36+col0]   = f2tf_f(v10);
            Ss[r1*36+col0+1] = f2tf_f(v11);
        }
        __syncthreads();
        // ---- acc += S @ V (64x256, K=32) ----
        #pragma unroll
        for (int k8=0;k8<32;k8+=8){
            uint32_t a0=__float_as_uint(Ss[(wmP+gr  )*36 + k8+ct  ]);
            uint32_t a1=__float_as_uint(Ss[(wmP+gr+8)*36 + k8+ct  ]);
            uint32_t a2=__float_as_uint(Ss[(wmP+gr  )*36 + k8+ct+4]);
            uint32_t a3=__float_as_uint(Ss[(wmP+gr+8)*36 + k8+ct+4]);
            #pragma unroll
            for (int nt=0;nt<16;nt++){
                uint32_t b0=f2tf(Vs[(k8+ct  )*264 + wnP + nt*8 + gr]);
                uint32_t b1=f2tf(Vs[(k8+ct+4)*264 + wnP + nt*8 + gr]);
                mma8(acc[nt], a0,a1,a2,a3, b0,b1);
            }
        }
        __syncthreads();
    }
    float* P = g_part + (((size_t)(head*8 + kc))*BL + (size_t)b*2048 + (size_t)qt*64)*256;
    #pragma unroll
    for (int nt=0;nt<16;nt++){
        int col = wnP + nt*8 + 2*ct;
        int r0 = wmP + gr, r1 = r0 + 8;
        *(float2*)(P + (size_t)r0*256 + col) = make_float2(acc[nt][0], acc[nt][1]);
        *(float2*)(P + (size_t)r1*256 + col) = make_float2(acc[nt][2], acc[nt][3]);
    }
}

// ---------------- layernorm (sums partials) ----------------
__global__ __launch_bounds__(256) void k_ln(const float* __restrict__ lng,
                                            const float* __restrict__ lnb){
    int row = blockIdx.x, t = threadIdx.x;
    int l = row & 2047;
    int nch = ((l >> 6) >> 2) + 1;
    float c = 0.f;
    for (int kc=0; kc<nch; kc++){
        c += g_part[(((size_t)kc)*BL + row)*256 + t];
        c += g_part[(((size_t)(8+kc))*BL + row)*256 + t];
    }
    float s = c, q = c*c;
    #pragma unroll
    for (int o=16;o>0;o>>=1){
        s += __shfl_down_sync(0xffffffffu, s, o);
        q += __shfl_down_sync(0xffffffffu, q, o);
    }
    __shared__ float ws[8], wq[8];
    __shared__ float mu_s, inv_s;
    if ((t&31)==0){ ws[t>>5]=s; wq[t>>5]=q; }
    __syncthreads();
    if (t==0){
        float S=0.f, Qq=0.f;
        #pragma unroll
        for (int i=0;i<8;i++){ S+=ws[i]; Qq+=wq[i]; }
        float mu = S*(1.0f/256.0f);
        float var = Qq*(1.0f/256.0f) - mu*mu;
        mu_s = mu; inv_s = rsqrtf(var + 1e-5f);
    }
    __syncthreads();
    float v = (c - mu_s)*inv_s*lng[t] + lnb[t];
    g_ctx[(size_t)row*DD + t] = v;
}

// ---------------- launch ----------------
extern "C" void kernel_launch(void* const* d_in, const int* in_sizes, int n_in,
                              void* d_out, int out_size){
    const float* x         = (const float*)d_in[0];
    const float* pos       = (const float*)d_in[1];
    const float* w_content = (const float*)d_in[2];
    const float* b_content = (const float*)d_in[3];
    const float* hop_w1    = (const float*)d_in[4];
    const float* hop_b1    = (const float*)d_in[5];
    const float* hop_w2    = (const float*)d_in[6];
    const float* hop_b2    = (const float*)d_in[7];
    const float* w_cpe     = (const float*)d_in[8];
    const float* b_cpe     = (const float*)d_in[9];
    const float* w_val     = (const float*)d_in[10];
    const float* b_val     = (const float*)d_in[11];
    const float* w_ctx     = (const float*)d_in[12];
    const float* b_ctx     = (const float*)d_in[13];
    const float* kv_w1     = (const float*)d_in[14];
    const float* kv_b1     = (const float*)d_in[15];
    const float* kv_w2     = (const float*)d_in[16];
    const float* kv_b2     = (const float*)d_in[17];
    const float* sg_w1     = (const float*)d_in[18];
    const float* sg_b1     = (const float*)d_in[19];
    const float* sg_w2     = (const float*)d_in[20];
    const float* sg_b2     = (const float*)d_in[21];
    const float* ln_g      = (const float*)d_in[22];
    const float* ln_b      = (const float*)d_in[23];
    const float* w_out     = (const float*)d_in[24];
    const float* b_out     = (const float*)d_in[25];
    float* out = (float*)d_out;

    float *p_content, *p_values, *p_ctx, *p_sgh, *p_cpe, *p_offin, *p_h1,
          *p_storage, *p_kvh, *p_sp, *p_w2bd, *p_off;
    cudaGetSymbolAddress((void**)&p_content, g_content);
    cudaGetSymbolAddress((void**)&p_values , g_values );
    cudaGetSymbolAddress((void**)&p_ctx    , g_ctx    );
    cudaGetSymbolAddress((void**)&p_sgh    , g_sgh    );
    cudaGetSymbolAddress((void**)&p_cpe    , g_cpe    );
    cudaGetSymbolAddress((void**)&p_offin  , g_offin  );
    cudaGetSymbolAddress((void**)&p_h1     , g_h1     );
    cudaGetSymbolAddress((void**)&p_storage, g_storage);
    cudaGetSymbolAddress((void**)&p_kvh    , g_kvh    );
    cudaGetSymbolAddress((void**)&p_sp     , g_sp     );
    cudaGetSymbolAddress((void**)&p_w2bd   , g_w2bd   );
    cudaGetSymbolAddress((void**)&p_off    , g_off    );

    cudaFuncSetAttribute(k_attn, cudaFuncAttributeMaxDynamicSharedMemorySize,
                         ATTN_SMEM_FLOATS*4);

    k_prep<<<BL, 256>>>(x, pos, hop_w2);

    k_gemm_multi_t<<<dim3(64,23), 128>>>(x,
        w_content, b_content, p_content,
        w_val,     b_val,     p_values,
        w_ctx,     b_ctx,     p_ctx,
        sg_w1,     sg_b1,     p_sgh,
        w_cpe,     b_cpe,     p_cpe,
        hop_w1,    hop_b1,    p_h1,
        p_offin);

    // hop layer 2 as block-diagonal GEMM: off = h1 @ W2bd^T  (M=4096, N=132, K=512)
    k_gemm_t<<<dim3(64,3), 128>>>(p_h1, p_w2bd, hop_b2, nullptr, p_off, 512, 132, 0, 132, 0);

    k_hop2<<<BL, 256>>>(pos, sg_w2, sg_b2);

    k_scan1<<<dim3(BB,64), 256>>>();
    k_scan2<<<dim3(BB,64), 256>>>();
    k_scang<<<BB, 32>>>();

    k_gemm_t<<<dim3(64,4), 128>>>(p_storage, kv_w1, kv_b1, nullptr, p_kvh, 512, 256, 1, 0, 0);
    k_gemm_t<<<dim3(64,1), 128>>>(p_kvh,     kv_w2, kv_b2, nullptr, p_sp,  256, 32,  0, 32, 0);

    k_build2<<<BL/8, 256>>>();

    k_attn<<<dim3(144, BB, 2), 256, ATTN_SMEM_FLOATS*4>>>();

    k_ln<<<BL, 256>>>(ln_g, ln_b);
    k_gemm_t<<<dim3(64,4), 128>>>(p_ctx, w_out, b_out, x, out, 256, 256, 0, 0, 1);
}

// round 7
// speedup vs baseline: 6.8273x; 1.0833x over previous
#include <cuda_runtime.h>
#include <math.h>
#include <stdint.h>

#define LL 2048
#define BB 2
#define DD 256
#define PP 32
#define BL (BB*LL)

// ---------------- scratch ----------------
__device__ __align__(256) float g_content[BL*DD];
__device__ __align__(256) float g_values [BL*DD];
__device__ __align__(256) float g_ctx    [BL*DD];
__device__ __align__(256) float g_ctxavg [BL*DD];
__device__ __align__(256) float g_sgh    [BL*128];
__device__ __align__(256) float g_gate   [BL];
__device__ __align__(256) float g_gcum   [BL];
__device__ __align__(256) float g_cpe    [BL*PP];
__device__ __align__(256) float g_h1     [BL*512];
__device__ __align__(256) float g_Q1     [BL*64];
__device__ __align__(256) float g_K1     [LL*64];
__device__ __align__(256) float g_kvh    [BL*256];
__device__ __align__(256) float g_sp     [BL*PP];
__device__ __align__(256) float g_Q2     [BL*64];
__device__ __align__(256) float g_K2     [BL*64];
__device__ __align__(256) float g_csum   [BB*64*256];
__device__ __align__(256) float g_w2bd   [132*512];
__device__ __align__(256) float g_off    [BL*132];
__device__ __align__(256) float g_part   [2u*8u*BL*DD];   // [head][kc][row][col]

__device__ __forceinline__ float gelu_f(float v){
    return 0.5f*v*(1.0f + erff(v*0.70710678118654752f));
}

// ---------------- tf32 / async helpers ----------------
__device__ __forceinline__ uint32_t f2tf(float f){
    uint32_t u; asm("cvt.rna.tf32.f32 %0, %1;" : "=r"(u) : "f"(f)); return u;
}
__device__ __forceinline__ float f2tf_f(float f){ return __uint_as_float(f2tf(f)); }

__device__ __forceinline__ void mma8(float* c,
        uint32_t a0,uint32_t a1,uint32_t a2,uint32_t a3,
        uint32_t b0,uint32_t b1){
    asm volatile("mma.sync.aligned.m16n8k8.row.col.f32.tf32.tf32.f32 "
        "{%0,%1,%2,%3},{%4,%5,%6,%7},{%8,%9},{%0,%1,%2,%3};"
        : "+f"(c[0]),"+f"(c[1]),"+f"(c[2]),"+f"(c[3])
        : "r"(a0),"r"(a1),"r"(a2),"r"(a3),"r"(b0),"r"(b1));
}

__device__ __forceinline__ void cpasync16(void* s, const void* g){
    uint32_t sa = (uint32_t)__cvta_generic_to_shared(s);
    asm volatile("cp.async.cg.shared.global [%0], [%1], 16;" :: "r"(sa), "l"(g));
}
__device__ __forceinline__ void cp_commit(){ asm volatile("cp.async.commit_group;"); }
__device__ __forceinline__ void cp_wait0(){ asm volatile("cp.async.wait_group 0;" ::: "memory"); }

// split-A load: cols < Ksplit from A (stride sA), else from A2 (stride sA2)
__device__ __forceinline__ float4 ldA4(const float* __restrict__ A,
        const float* __restrict__ A2, int sA, int sA2, int Ksplit, int modA2,
        int row, int col){
    if (!A2 || col < Ksplit)
        return *(const float4*)(A + (size_t)row*sA + col);
    int r2 = modA2 ? (row & 2047) : row;
    return *(const float4*)(A2 + (size_t)r2*sA2 + (col - Ksplit));
}

// ---------------- tf32 GEMM core (register-prefetch pipelined, split-A) ----------------
__device__ __forceinline__ void gemm_core(const float* __restrict__ A,
        const float* __restrict__ A2, int sA, int sA2, int Ksplit, int modA2,
        const float* __restrict__ W, const float* __restrict__ bias,
        const float* __restrict__ addend, float* __restrict__ C,
        int K, int N, int bm, int bn, bool act, int Nlim, bool addres,
        float (*As)[20], float (*Ws)[20]){
    int t = threadIdx.x;
    int w = t>>5, lane = t&31, gr = lane>>2, ct = lane&3;
    int wm = (w&1)*32, wn = (w>>1)*32;
    int r0 = t>>2, c4 = (t&3)*4;
    float acc[2][4][4];
    #pragma unroll
    for (int mt=0;mt<2;mt++)
        #pragma unroll
        for (int nt=0;nt<4;nt++)
            #pragma unroll
            for (int i=0;i<4;i++) acc[mt][nt][i]=0.f;

    int g0 = bn+r0, g1 = bn+r0+32;
    if (Nlim){ if (g0>=Nlim) g0=Nlim-1; if (g1>=Nlim) g1=Nlim-1; }
    const float* Wr0 = W + (size_t)g0*K + c4;
    const float* Wr1 = W + (size_t)g1*K + c4;
    float4 pa0 = ldA4(A,A2,sA,sA2,Ksplit,modA2, bm+r0,    c4);
    float4 pa1 = ldA4(A,A2,sA,sA2,Ksplit,modA2, bm+r0+32, c4);
    float4 pw0 = *(const float4*)Wr0;
    float4 pw1 = *(const float4*)Wr1;

    for (int k0=0; k0<K; k0+=16){
        As[r0   ][c4+0]=f2tf_f(pa0.x); As[r0   ][c4+1]=f2tf_f(pa0.y);
        As[r0   ][c4+2]=f2tf_f(pa0.z); As[r0   ][c4+3]=f2tf_f(pa0.w);
        As[r0+32][c4+0]=f2tf_f(pa1.x); As[r0+32][c4+1]=f2tf_f(pa1.y);
        As[r0+32][c4+2]=f2tf_f(pa1.z); As[r0+32][c4+3]=f2tf_f(pa1.w);
        Ws[r0   ][c4+0]=f2tf_f(pw0.x); Ws[r0   ][c4+1]=f2tf_f(pw0.y);
        Ws[r0   ][c4+2]=f2tf_f(pw0.z); Ws[r0   ][c4+3]=f2tf_f(pw0.w);
        Ws[r0+32][c4+0]=f2tf_f(pw1.x); Ws[r0+32][c4+1]=f2tf_f(pw1.y);
        Ws[r0+32][c4+2]=f2tf_f(pw1.z); Ws[r0+32][c4+3]=f2tf_f(pw1.w);
        __syncthreads();
        if (k0+16 < K){
            pa0 = ldA4(A,A2,sA,sA2,Ksplit,modA2, bm+r0,    k0+16+c4);
            pa1 = ldA4(A,A2,sA,sA2,Ksplit,modA2, bm+r0+32, k0+16+c4);
            pw0 = *(const float4*)(Wr0 + k0+16);
            pw1 = *(const float4*)(Wr1 + k0+16);
        }
        #pragma unroll
        for (int k8=0;k8<16;k8+=8){
            uint32_t a[2][4];
            #pragma unroll
            for (int mt=0;mt<2;mt++){
                a[mt][0]=__float_as_uint(As[wm+mt*16+gr  ][k8+ct  ]);
                a[mt][1]=__float_as_uint(As[wm+mt*16+gr+8][k8+ct  ]);
                a[mt][2]=__float_as_uint(As[wm+mt*16+gr  ][k8+ct+4]);
                a[mt][3]=__float_as_uint(As[wm+mt*16+gr+8][k8+ct+4]);
            }
            #pragma unroll
            for (int nt=0;nt<4;nt++){
                uint32_t b0=__float_as_uint(Ws[wn+nt*8+gr][k8+ct  ]);
                uint32_t b1=__float_as_uint(Ws[wn+nt*8+gr][k8+ct+4]);
                #pragma unroll
                for (int mt=0;mt<2;mt++)
                    mma8(acc[mt][nt], a[mt][0],a[mt][1],a[mt][2],a[mt][3], b0,b1);
            }
        }
        __syncthreads();
    }
    #pragma unroll
    for (int mt=0;mt<2;mt++){
        #pragma unroll
        for (int nt=0;nt<4;nt++){
            int col = bn + wn + nt*8 + 2*ct;
            if (Nlim && col >= Nlim) continue;
            int rr0 = bm + wm + mt*16 + gr;
            int rr1 = rr0 + 8;
            float b0v = bias[col], b1v = bias[col+1];
            float v00 = acc[mt][nt][0] + b0v;
            float v01 = acc[mt][nt][1] + b1v;
            float v10 = acc[mt][nt][2] + b0v;
            float v11 = acc[mt][nt][3] + b1v;
            if (act){ v00=gelu_f(v00); v01=gelu_f(v01); v10=gelu_f(v10); v11=gelu_f(v11); }
            if (addres){
                v00 += addend[(size_t)rr0*N+col]; v01 += addend[(size_t)rr0*N+col+1];
                v10 += addend[(size_t)rr1*N+col]; v11 += addend[(size_t)rr1*N+col+1];
            }
            C[(size_t)rr0*N+col]   = v00;
            C[(size_t)rr0*N+col+1] = v01;
            C[(size_t)rr1*N+col]   = v10;
            C[(size_t)rr1*N+col+1] = v11;
        }
    }
}

// ---------------- merged GEMM: 5 x-projections + hop layer1 (grid.y = 23) ----------------
__global__ __launch_bounds__(128) void k_gemm_multi_t(const float* __restrict__ x,
        const float* __restrict__ pos,
        const float* __restrict__ w_content, const float* __restrict__ b_content, float* __restrict__ p_content,
        const float* __restrict__ w_val,     const float* __restrict__ b_val,     float* __restrict__ p_values,
        const float* __restrict__ w_ctx,     const float* __restrict__ b_ctx,     float* __restrict__ p_ctx,
        const float* __restrict__ sg_w1,     const float* __restrict__ sg_b1,     float* __restrict__ p_sgh,
        const float* __restrict__ w_cpe,     const float* __restrict__ b_cpe,     float* __restrict__ p_cpe,
        const float* __restrict__ hop_w1,    const float* __restrict__ hop_b1,    float* __restrict__ p_h1){
    __shared__ float As[64][20];
    __shared__ float Ws[64][20];
    int y = blockIdx.y;
    int seg, bn, N, K, Nlim=0; bool act=false;
    const float* A2 = nullptr; int modA2 = 0;
    if (y < 12){ seg = y>>2; bn = (y&3)*64; N = 256; K = 256; }
    else if (y < 14){ seg = 3; bn = (y-12)*64; N = 128; K = 256; act = true; }
    else if (y == 14){ seg = 4; bn = 0; N = 32; K = 256; Nlim = 32; }
    else { seg = 5; bn = (y-15)*64; N = 512; K = 288; act = true; A2 = pos; modA2 = 1; }
    const float* W; const float* Bv; float* C;
    if      (seg==0){ W=w_content; Bv=b_content; C=p_content; }
    else if (seg==1){ W=w_val;     Bv=b_val;     C=p_values;  }
    else if (seg==2){ W=w_ctx;     Bv=b_ctx;     C=p_ctx;     }
    else if (seg==3){ W=sg_w1;     Bv=sg_b1;     C=p_sgh;     }
    else if (seg==4){ W=w_cpe;     Bv=b_cpe;     C=p_cpe;     }
    else            { W=hop_w1;    Bv=hop_b1;    C=p_h1;      }
    gemm_core(x, A2, 256, 32, 256, modA2, W, Bv, nullptr, C,
              K, N, blockIdx.x*64, bn, act, Nlim, false, As, Ws);
}

// ---------------- generic single tf32 GEMM ----------------
__global__ __launch_bounds__(128) void k_gemm_t(const float* __restrict__ A,
        const float* __restrict__ A2, int sA, int sA2, int Ksplit,
        const float* __restrict__ W, const float* __restrict__ bias,
        const float* __restrict__ addend, float* __restrict__ C,
        int K, int N, int act, int Nlim, int addres){
    __shared__ float As[64][20];
    __shared__ float Ws[64][20];
    gemm_core(A, A2, sA, sA2, Ksplit, 0, W, bias, addend, C, K, N,
              blockIdx.x*64, blockIdx.y*64, act!=0, Nlim, addres!=0, As, Ws);
}

// ---------------- prep: K1 trig + block-diagonal hop_w2 (grid 264) ----------------
__global__ __launch_bounds__(256) void k_prep(const float* __restrict__ pos,
                                              const float* __restrict__ hop_w2){
    int idx = blockIdx.x*256 + threadIdx.x;
    if (idx < 65536){
        int l = idx >> 5, p = idx & 31;
        float s, c; sincosf(pos[l*PP + p], &s, &c);
        g_K1[l*64 + p] = c; g_K1[l*64 + 32 + p] = s;
    }
    if (idx < 132*512){
        int o = idx >> 9, c = idx & 511;
        int h = o / 33;
        int g = c - (h<<7);
        g_w2bd[idx] = (g >= 0 && g < 128) ? hop_w2[o*128 + g] : 0.f;
    }
}

// ---------------- hop epilogue: off -> coefs/Q1; gate ----------------
__global__ __launch_bounds__(256) void k_hop2(const float* __restrict__ pos,
        const float* __restrict__ sg_w2, const float* __restrict__ sg_b2){
    int row = blockIdx.x; int t = threadIdx.x;
    int l = row & 2047;
    __shared__ float offs[132];
    __shared__ float coefs[4];
    __shared__ float wsum[4];
    if (t < 132) offs[t] = g_off[(size_t)row*132 + t];
    float p = (t < 128) ? g_sgh[(size_t)row*128 + t]*sg_w2[t] : 0.f;
    #pragma unroll
    for (int off=16; off>0; off>>=1) p += __shfl_down_sync(0xffffffffu, p, off);
    if ((t&31)==0 && t<128) wsum[t>>5] = p;
    __syncthreads();
    if (t == 0){
        float s = wsum[0]+wsum[1]+wsum[2]+wsum[3];
        g_gate[row] = 1.0f/(1.0f+expf(-(s + sg_b2[0])));
    }
    if (t >= 32 && t < 36){
        int h = t-32;
        float ww  = 2.0f/(1.0f+expf(-offs[h*33+32])) + 0.1f;
        float w2v = ww*ww + 1e-6f;
        float e1 = expf(-0.5f/w2v);
        float e2 = expf(-2.0f/w2v);
        float totw = 1.0f + 2.0f*e1 + 2.0f*e2;
        coefs[h] = (1.0f + 2.0f*e1*0.9950041652780258f + 2.0f*e2*0.9800665778412416f)
                   / (totw + 1e-6f);
    }
    __syncthreads();
    if (t < PP){
        float pp = pos[l*PP + t];
        float ac=0.f, as=0.f;
        #pragma unroll
        for (int h=0; h<4; h++){
            float th = pp + tanhf(offs[h*33+t])*3.14159265358979323846f;
            float s, c; sincosf(th, &s, &c);
            ac += coefs[h]*c; as += coefs[h]*s;
        }
        const float s0 = 0.04419417382415922f; // 1/(4*sqrt(32))
        g_Q1[(size_t)row*64 + t]      = ac*s0;
        g_Q1[(size_t)row*64 + 32 + t] = as*s0;
    }
}

// ---------------- chunked ctx_avg scan (64 chunks of 32 rows) ----------------
__global__ __launch_bounds__(256) void k_scan1(){ // grid(BB,64)
    int b = blockIdx.x, ch = blockIdx.y, t = threadIdx.x;
    const float* src = g_ctx + ((size_t)(b*2048 + ch*32))*256 + t;
    float s = 0.f;
    #pragma unroll 4
    for (int l=0; l<32; l++) s += src[(size_t)l*256];
    g_csum[(b*64+ch)*256 + t] = s;
}

__global__ __launch_bounds__(256) void k_scan2(){ // grid(BB,64)
    int b = blockIdx.x, ch = blockIdx.y, t = threadIdx.x;
    float run = 0.f;
    for (int j=0; j<ch; j++) run += g_csum[(b*64+j)*256 + t];
    const float* src = g_ctx + ((size_t)(b*2048 + ch*32))*256 + t;
    float* dst = g_ctxavg + ((size_t)(b*2048 + ch*32))*256 + t;
    int base = ch*32;
    #pragma unroll 4
    for (int l=0; l<32; l++){
        run += src[(size_t)l*256];
        dst[(size_t)l*256] = run / (float)(base + l + 1);
    }
}

__global__ void k_scang(){ // grid(BB), 32 thr
    int b = blockIdx.x, lane = threadIdx.x;
    float carry = 0.f;
    for (int l0=0; l0<LL; l0+=32){
        float v = g_gate[b*LL + l0 + lane];
        #pragma unroll
        for (int o=1;o<32;o<<=1){
            float n = __shfl_up_sync(0xffffffffu, v, o);
            if (lane >= o) v += n;
        }
        float tot = __shfl_sync(0xffffffffu, v, 31);
        g_gcum[b*LL + l0 + lane] = fmaxf(v + carry, 1.0f);
        carry += tot;
    }
}

// ---------------- Q2/K2 (gate folded into K2) ----------------
__global__ __launch_bounds__(256) void k_build2(){
    int row = blockIdx.x*8 + (threadIdx.x>>5);
    int t = threadIdx.x&31;
    const float PIf = 3.14159265358979323846f;
    float gv = g_gate[row];
    float spv = tanhf(g_sp[(size_t)row*PP + t])*PIf;
    float s, c; sincosf(spv, &s, &c);
    g_K2[(size_t)row*64 + t]      = c*gv;
    g_K2[(size_t)row*64 + 32 + t] = s*gv;
    float kp  = tanhf(g_cpe[(size_t)row*PP + t])*PIf;
    float inv = rsqrtf(g_gcum[row]) * 0.1767766952966369f; // 1/sqrt(32)
    sincosf(kp, &s, &c);
    g_Q2[(size_t)row*64 + t]      = c*inv;
    g_Q2[(size_t)row*64 + 32 + t] = s*inv;
}

// ---------------- split-KV causal attention (tf32 mma, cp.async double-buffered) ------
#define ATTN_SMEM_FLOATS (4352+2304+4352+16896)
__global__ __launch_bounds__(256,2) void k_attn(){
    int head = blockIdx.z, b = blockIdx.y;
    int id = blockIdx.x;                    // 0..143
    int g = 0;
    while (id >= 2*(g+1)*(g+2)) g++;
    int e  = id - 2*g*(g+1);
    int qt = 4*g + e/(g+1);
    int kc = e - (e/(g+1))*(g+1);
    int kt0 = kc*8;
    int ktend = 2*qt + 2; if (ktend > kt0+8) ktend = kt0+8;

    extern __shared__ float sm[];
    float* Qs  = sm;                    // [64][68]
    float* Ss  = sm + 4352;             // [64][36]
    float* Kb0 = sm + 6656;             // [32][68]
    float* Kb1 = sm + 8832;
    float* Vb0 = sm + 11008;            // [32][264]
    float* Vb1 = sm + 19456;

    const float* Q  = head ? g_Q2 + (size_t)b*LL*64 : g_Q1 + (size_t)b*LL*64;
    const float* Kp = head ? g_K2 + (size_t)b*LL*64 : g_K1;
    const float* V  = head ? g_values + (size_t)b*LL*DD : g_content + (size_t)b*LL*DD;

    int t = threadIdx.x;
    int w = t>>5, lane = t&31, gr = lane>>2, ct = lane&3;

    {
        const float* Kt = Kp + (size_t)kt0*2048;
        const float* Vt = V  + (size_t)kt0*8192;
        #pragma unroll
        for (int i=0;i<2;i++){
            int c = t*2+i; int r=c>>4, c4=(c&15)*4;
            cpasync16(Kb0 + r*68 + c4, Kt + r*64 + c4);
        }
        #pragma unroll
        for (int i=0;i<8;i++){
            int c = t + 256*i; int r=c>>6, c4=(c&63)*4;
            cpasync16(Vb0 + r*264 + c4, Vt + r*256 + c4);
        }
        cp_commit();
    }

    const float* Qt = Q + (size_t)qt*64*64;
    for (int idx=t; idx<4096; idx+=256)
        Qs[(idx>>6)*68 + (idx&63)] = f2tf_f(Qt[idx]);

    float acc[16][4];
    #pragma unroll
    for (int i=0;i<16;i++){ acc[i][0]=0.f; acc[i][1]=0.f; acc[i][2]=0.f; acc[i][3]=0.f; }

    int wmS = (w&3)*16, wnS = (w>>2)*16;
    int wmP = (w&3)*16, wnP = (w>>2)*128;
    int buf = 0;

    for (int kt=kt0; kt<ktend; kt++, buf^=1){
        cp_wait0();
        __syncthreads();
        if (kt+1 < ktend){
            float* Kd = buf ? Kb0 : Kb1;
            float* Vd = buf ? Vb0 : Vb1;
            const float* Kt = Kp + (size_t)(kt+1)*2048;
            const float* Vt = V  + (size_t)(kt+1)*8192;
            #pragma unroll
            for (int i=0;i<2;i++){
                int c = t*2+i; int r=c>>4, c4=(c&15)*4;
                cpasync16(Kd + r*68 + c4, Kt + r*64 + c4);
            }
            #pragma unroll
            for (int i=0;i<8;i++){
                int c = t + 256*i; int r=c>>6, c4=(c&63)*4;
                cpasync16(Vd + r*264 + c4, Vt + r*256 + c4);
            }
            cp_commit();
        }
        const float* Ks = buf ? Kb1 : Kb0;
        const float* Vs = buf ? Vb1 : Vb0;
        // ---- S = Q @ K^T ----
        float cS[2][4];
        #pragma unroll
        for (int nt=0;nt<2;nt++){ cS[nt][0]=0.f; cS[nt][1]=0.f; cS[nt][2]=0.f; cS[nt][3]=0.f; }
        #pragma unroll
        for (int k8=0;k8<64;k8+=8){
            uint32_t a0=__float_as_uint(Qs[(wmS+gr  )*68 + k8+ct  ]);
            uint32_t a1=__float_as_uint(Qs[(wmS+gr+8)*68 + k8+ct  ]);
            uint32_t a2=__float_as_uint(Qs[(wmS+gr  )*68 + k8+ct+4]);
            uint32_t a3=__float_as_uint(Qs[(wmS+gr+8)*68 + k8+ct+4]);
            #pragma unroll
            for (int nt=0;nt<2;nt++){
                uint32_t b0=f2tf(Ks[(wnS+nt*8+gr)*68 + k8+ct  ]);
                uint32_t b1=f2tf(Ks[(wnS+nt*8+gr)*68 + k8+ct+4]);
                mma8(cS[nt], a0,a1,a2,a3, b0,b1);
            }
        }
        bool diag = (kt >= 2*qt);
        #pragma unroll
        for (int nt=0;nt<2;nt++){
            int col0 = wnS + nt*8 + 2*ct;
            int r0 = wmS + gr, r1 = r0 + 8;
            float v00=cS[nt][0], v01=cS[nt][1], v10=cS[nt][2], v11=cS[nt][3];
            if (diag){
                int gcol = kt*32 + col0;
                int grow0 = qt*64 + r0, grow1 = qt*64 + r1;
                if (gcol   > grow0) v00 = 0.f;
                if (gcol+1 > grow0) v01 = 0.f;
                if (gcol   > grow1) v10 = 0.f;
                if (gcol+1 > grow1) v11 = 0.f;
            }
            Ss[r0*36+col0]   = f2tf_f(v00);
            Ss[r0*36+col0+1] = f2tf_f(v01);
            Ss[r1*36+col0]   = f2tf_f(v10);
            Ss[r1*36+col0+1] = f2tf_f(v11);
        }
        __syncthreads();
        // ---- acc += S @ V ----
        #pragma unroll
        for (int k8=0;k8<32;k8+=8){
            uint32_t a0=__float_as_uint(Ss[(wmP+gr  )*36 + k8+ct  ]);
            uint32_t a1=__float_as_uint(Ss[(wmP+gr+8)*36 + k8+ct  ]);
            uint32_t a2=__float_as_uint(Ss[(wmP+gr  )*36 + k8+ct+4]);
            uint32_t a3=__float_as_uint(Ss[(wmP+gr+8)*36 + k8+ct+4]);
            #pragma unroll
            for (int nt=0;nt<16;nt++){
                uint32_t b0=f2tf(Vs[(k8+ct  )*264 + wnP + nt*8 + gr]);
                uint32_t b1=f2tf(Vs[(k8+ct+4)*264 + wnP + nt*8 + gr]);
                mma8(acc[nt], a0,a1,a2,a3, b0,b1);
            }
        }
        __syncthreads();
    }
    float* P = g_part + (((size_t)(head*8 + kc))*BL + (size_t)b*2048 + (size_t)qt*64)*256;
    #pragma unroll
    for (int nt=0;nt<16;nt++){
        int col = wnP + nt*8 + 2*ct;
        int r0 = wmP + gr, r1 = r0 + 8;
        *(float2*)(P + (size_t)r0*256 + col) = make_float2(acc[nt][0], acc[nt][1]);
        *(float2*)(P + (size_t)r1*256 + col) = make_float2(acc[nt][2], acc[nt][3]);
    }
}

// ---------------- layernorm (sums partials) ----------------
__global__ __launch_bounds__(256) void k_ln(const float* __restrict__ lng,
                                            const float* __restrict__ lnb){
    int row = blockIdx.x, t = threadIdx.x;
    int l = row & 2047;
    int nch = ((l >> 6) >> 2) + 1;
    float c = 0.f;
    for (int kc=0; kc<nch; kc++){
        c += g_part[(((size_t)kc)*BL + row)*256 + t];
        c += g_part[(((size_t)(8+kc))*BL + row)*256 + t];
    }
    float s = c, q = c*c;
    #pragma unroll
    for (int o=16;o>0;o>>=1){
        s += __shfl_down_sync(0xffffffffu, s, o);
        q += __shfl_down_sync(0xffffffffu, q, o);
    }
    __shared__ float ws[8], wq[8];
    __shared__ float mu_s, inv_s;
    if ((t&31)==0){ ws[t>>5]=s; wq[t>>5]=q; }
    __syncthreads();
    if (t==0){
        float S=0.f, Qq=0.f;
        #pragma unroll
        for (int i=0;i<8;i++){ S+=ws[i]; Qq+=wq[i]; }
        float mu = S*(1.0f/256.0f);
        float var = Qq*(1.0f/256.0f) - mu*mu;
        mu_s = mu; inv_s = rsqrtf(var + 1e-5f);
    }
    __syncthreads();
    float v = (c - mu_s)*inv_s*lng[t] + lnb[t];
    g_ctx[(size_t)row*DD + t] = v;
}

// ---------------- launch ----------------
extern "C" void kernel_launch(void* const* d_in, const int* in_sizes, int n_in,
                              void* d_out, int out_size){
    const float* x         = (const float*)d_in[0];
    const float* pos       = (const float*)d_in[1];
    const float* w_content = (const float*)d_in[2];
    const float* b_content = (const float*)d_in[3];
    const float* hop_w1    = (const float*)d_in[4];
    const float* hop_b1    = (const float*)d_in[5];
    const float* hop_w2    = (const float*)d_in[6];
    const float* hop_b2    = (const float*)d_in[7];
    const float* w_cpe     = (const float*)d_in[8];
    const float* b_cpe     = (const float*)d_in[9];
    const float* w_val     = (const float*)d_in[10];
    const float* b_val     = (const float*)d_in[11];
    const float* w_ctx     = (const float*)d_in[12];
    const float* b_ctx     = (const float*)d_in[13];
    const float* kv_w1     = (const float*)d_in[14];
    const float* kv_b1     = (const float*)d_in[15];
    const float* kv_w2     = (const float*)d_in[16];
    const float* kv_b2     = (const float*)d_in[17];
    const float* sg_w1     = (const float*)d_in[18];
    const float* sg_b1     = (const float*)d_in[19];
    const float* sg_w2     = (const float*)d_in[20];
    const float* sg_b2     = (const float*)d_in[21];
    const float* ln_g      = (const float*)d_in[22];
    const float* ln_b      = (const float*)d_in[23];
    const float* w_out     = (const float*)d_in[24];
    const float* b_out     = (const float*)d_in[25];
    float* out = (float*)d_out;

    float *p_content, *p_values, *p_ctx, *p_ctxavg, *p_sgh, *p_cpe, *p_h1,
          *p_kvh, *p_sp, *p_w2bd, *p_off;
    cudaGetSymbolAddress((void**)&p_content, g_content);
    cudaGetSymbolAddress((void**)&p_values , g_values );
    cudaGetSymbolAddress((void**)&p_ctx    , g_ctx    );
    cudaGetSymbolAddress((void**)&p_ctxavg , g_ctxavg );
    cudaGetSymbolAddress((void**)&p_sgh    , g_sgh    );
    cudaGetSymbolAddress((void**)&p_cpe    , g_cpe    );
    cudaGetSymbolAddress((void**)&p_h1     , g_h1     );
    cudaGetSymbolAddress((void**)&p_kvh    , g_kvh    );
    cudaGetSymbolAddress((void**)&p_sp     , g_sp     );
    cudaGetSymbolAddress((void**)&p_w2bd   , g_w2bd   );
    cudaGetSymbolAddress((void**)&p_off    , g_off    );

    cudaFuncSetAttribute(k_attn, cudaFuncAttributeMaxDynamicSharedMemorySize,
                         ATTN_SMEM_FLOATS*4);

    k_prep<<<264, 256>>>(pos, hop_w2);

    k_gemm_multi_t<<<dim3(64,23), 128>>>(x, pos,
        w_content, b_content, p_content,
        w_val,     b_val,     p_values,
        w_ctx,     b_ctx,     p_ctx,
        sg_w1,     sg_b1,     p_sgh,
        w_cpe,     b_cpe,     p_cpe,
        hop_w1,    hop_b1,    p_h1);

    // hop layer 2 as block-diagonal GEMM: off = h1 @ W2bd^T  (M=4096, N=132, K=512)
    k_gemm_t<<<dim3(64,3), 128>>>(p_h1, nullptr, 512, 0, 0,
        p_w2bd, hop_b2, nullptr, p_off, 512, 132, 0, 132, 0);

    k_hop2<<<BL, 256>>>(pos, sg_w2, sg_b2);

    k_scan1<<<dim3(BB,64), 256>>>();
    k_scan2<<<dim3(BB,64), 256>>>();
    k_scang<<<BB, 32>>>();

    // kv MLP: storage_in = [x, ctx_avg] via split-A
    k_gemm_t<<<dim3(64,4), 128>>>(x, p_ctxavg, 256, 256, 256,
        kv_w1, kv_b1, nullptr, p_kvh, 512, 256, 1, 0, 0);
    k_gemm_t<<<dim3(64,1), 128>>>(p_kvh, nullptr, 256, 0, 0,
        kv_w2, kv_b2, nullptr, p_sp, 256, 32, 0, 32, 0);

    k_build2<<<BL/8, 256>>>();

    k_attn<<<dim3(144, BB, 2), 256, ATTN_SMEM_FLOATS*4>>>();

    k_ln<<<BL, 256>>>(ln_g, ln_b);
    k_gemm_t<<<dim3(64,4), 128>>>(p_ctx, nullptr, 256, 0, 0,
        w_out, b_out, x, out, 256, 256, 0, 0, 1);
}